// round 11
// baseline (speedup 1.0000x reference)
#include <cuda_runtime.h>
#include <cuda_bf16.h>
#include <math.h>
#include <stdint.h>

// ---------------- problem constants ----------------
#define NG    128
#define NPG   256
#define DF    128
#define KBINS 16
#define NBINC 12               // computed bins (12..15 analytically ~0)
#define NSLOT 256

#define INV_TEMP 2.0f
#define LAMBDA   0.1f
#define GA (-0.82073318f)      // a*log2(e), a = -0.5/(0.9375^2)

// ---------------- device scratch ----------------
__device__ __nv_bfloat16 g_Dbf[(size_t)NSLOT * NPG * NPG];   // distances (3 of 4 quadrants)
__device__ float g_sumD[NSLOT];
__device__ float g_hpart[NSLOT * 2 * KBINS];
__device__ float g_rowloss[NSLOT];
__device__ float4 g_znT4[32 * NSLOT];      // [k4][row]
__device__ float g_znR[NSLOT * DF];
__device__ int   g_ticket;

// ---------------- helpers ----------------
static __device__ __forceinline__ uint32_t smem_u32(const void* p) {
    uint32_t a;
    asm("{ .reg .u64 t; cvta.to.shared.u64 t, %1; cvt.u32.u64 %0, t; }" : "=r"(a) : "l"(p));
    return a;
}
static __device__ __forceinline__ unsigned long long pk2(float lo, float hi) {
    unsigned long long r;
    asm("mov.b64 %0, {%1, %2};" : "=l"(r) : "r"(__float_as_uint(lo)), "r"(__float_as_uint(hi)));
    return r;
}
static __device__ __forceinline__ unsigned long long mul2(unsigned long long a, unsigned long long b) {
    unsigned long long r;
    asm("mul.rn.f32x2 %0, %1, %2;" : "=l"(r) : "l"(a), "l"(b));
    return r;
}
static __device__ __forceinline__ unsigned long long add2(unsigned long long a, unsigned long long b) {
    unsigned long long r;
    asm("add.rn.f32x2 %0, %1, %2;" : "=l"(r) : "l"(a), "l"(b));
    return r;
}
static __device__ __forceinline__ unsigned long long ffma2(unsigned long long a, unsigned long long b, unsigned long long c) {
    unsigned long long r;
    asm("fma.rn.f32x2 %0, %1, %2, %3;" : "=l"(r) : "l"(a), "l"(b), "l"(c));
    return r;
}
static __device__ __forceinline__ void up2(unsigned long long v, float& lo, float& hi) {
    unsigned ulo, uhi;
    asm("mov.b64 {%0, %1}, %2;" : "=r"(ulo), "=r"(uhi) : "l"(v));
    lo = __uint_as_float(ulo); hi = __uint_as_float(uhi);
}
static __device__ __forceinline__ float ex2f(float x) {
    float r; asm("ex2.approx.f32 %0, %1;" : "=f"(r) : "f"(x)); return r;
}
static __device__ __forceinline__ void ldmx4(uint32_t& r0, uint32_t& r1, uint32_t& r2, uint32_t& r3, uint32_t addr) {
    asm volatile("ldmatrix.sync.aligned.m8n8.x4.shared.b16 {%0,%1,%2,%3}, [%4];"
                 : "=r"(r0), "=r"(r1), "=r"(r2), "=r"(r3) : "r"(addr));
}
static __device__ __forceinline__ void mma16816(float* c, uint32_t a0, uint32_t a1, uint32_t a2, uint32_t a3,
                                                uint32_t b0, uint32_t b1) {
    asm volatile("mma.sync.aligned.m16n8k16.row.col.f32.bf16.bf16.f32 "
                 "{%0,%1,%2,%3}, {%4,%5,%6,%7}, {%8,%9}, {%0,%1,%2,%3};"
                 : "+f"(c[0]), "+f"(c[1]), "+f"(c[2]), "+f"(c[3])
                 : "r"(a0), "r"(a1), "r"(a2), "r"(a3), "r"(b0), "r"(b1));
}
static __device__ __forceinline__ uint32_t tphys(int row, int kbyte) {
    return (uint32_t)(row * 256 + ((((kbyte >> 4) ^ (row & 7)) << 4) | (kbyte & 15)));
}

// ---------------- kernel 1: znorm (also resets final ticket) ----------------
__global__ __launch_bounds__(256) void k_znorm(const float* __restrict__ z1,
                                               const float* __restrict__ z2) {
    if (blockIdx.x == 0 && threadIdx.x == 0) g_ticket = 0;
    int wid = threadIdx.x >> 5;
    int lane = threadIdx.x & 31;
    int row = blockIdx.x * 8 + wid;
    const float* zr = (row < NG) ? (z1 + (size_t)row * DF) : (z2 + (size_t)(row - NG) * DF);
    float4 v = ((const float4*)zr)[lane];
    float ss = v.x * v.x + v.y * v.y + v.z * v.z + v.w * v.w;
    #pragma unroll
    for (int off = 16; off > 0; off >>= 1)
        ss += __shfl_down_sync(0xffffffffu, ss, off);
    float inv = 1.0f / (sqrtf(__shfl_sync(0xffffffffu, ss, 0)) + 1e-8f);
    float4 o = make_float4(v.x * inv, v.y * inv, v.z * inv, v.w * inv);
    ((float4*)(g_znR + (size_t)row * DF))[lane] = o;
    g_znT4[lane * NSLOT + row] = o;
}

// ---------------- kernel 2: HMMA Gram -> distances (bf16), one block per slot ----------------
__global__ __launch_bounds__(256, 2) void k_gemm(const float* __restrict__ H1,
                                                 const float* __restrict__ H2) {
    extern __shared__ char smraw[];                 // A: 256x128 bf16 swizzled = 64KB
    __shared__ float sq[256], rsum[8];

    int s = blockIdx.x;
    int g = s & (NG - 1);
    const float* H = (s < NG ? H1 : H2) + (size_t)g * NPG * DF;
    int tid = threadIdx.x;
    int lane = tid & 31;
    int wid = tid >> 5;

    #pragma unroll
    for (int it = 0; it < 16; it++) {
        int i = tid + it * 256;
        int row = i >> 4, u = i & 15;
        const float4* p = (const float4*)(H + (size_t)row * DF + u * 8);
        float4 v0 = p[0], v1 = p[1];
        __nv_bfloat162 h0 = __floats2bfloat162_rn(v0.x, v0.y);
        __nv_bfloat162 h1 = __floats2bfloat162_rn(v0.z, v0.w);
        __nv_bfloat162 h2 = __floats2bfloat162_rn(v1.x, v1.y);
        __nv_bfloat162 h3 = __floats2bfloat162_rn(v1.z, v1.w);
        uint4 st;
        st.x = *(uint32_t*)&h0; st.y = *(uint32_t*)&h1;
        st.z = *(uint32_t*)&h2; st.w = *(uint32_t*)&h3;
        *(uint4*)(smraw + tphys(row, u * 16)) = st;
        float2 f0 = __bfloat1622float2(h0), f1 = __bfloat1622float2(h1);
        float2 f2 = __bfloat1622float2(h2), f3 = __bfloat1622float2(h3);
        float ssq = f0.x * f0.x + f0.y * f0.y + f1.x * f1.x + f1.y * f1.y
                  + f2.x * f2.x + f2.y * f2.y + f3.x * f3.x + f3.y * f3.y;
        ssq += __shfl_down_sync(0xffffffffu, ssq, 8, 16);
        ssq += __shfl_down_sync(0xffffffffu, ssq, 4, 16);
        ssq += __shfl_down_sync(0xffffffffu, ssq, 2, 16);
        ssq += __shfl_down_sync(0xffffffffu, ssq, 1, 16);
        if ((lane & 15) == 0) sq[row] = ssq;
    }
    __syncthreads();

    int wr = (wid >> 1) * 32;
    int wc = (wid & 1) * 64;
    uint32_t smb = smem_u32(smraw);

    int gA = lane >> 3;
    int arow_off = (gA & 1) * 8 + (lane & 7);
    int akb_off  = (gA >> 1) * 16;
    int brow_off = (gA >> 1) * 8 + (lane & 7);
    int bkb_off  = (gA & 1) * 16;
    int lr = lane >> 2;
    int lc = (lane & 3) * 2;
    __nv_bfloat16* Dslot = g_Dbf + ((size_t)s << 16);

    float tsum = 0.f;

    #pragma unroll 1
    for (int m = 0; m < 3; m++) {
        int qr = (m == 2) ? 128 : 0;
        int qc = (m >= 1) ? 128 : 0;
        float w = (m == 1) ? 2.0f : 1.0f;

        float acc[2][8][4];
        #pragma unroll
        for (int mt = 0; mt < 2; mt++)
            #pragma unroll
            for (int nt = 0; nt < 8; nt++)
                #pragma unroll
                for (int e = 0; e < 4; e++) acc[mt][nt][e] = 0.f;

        #pragma unroll 1
        for (int ks = 0; ks < 8; ks++) {
            int kb = ks * 32;
            uint32_t a[2][4];
            #pragma unroll
            for (int mt = 0; mt < 2; mt++) {
                uint32_t addr = smb + tphys(qr + wr + mt * 16 + arow_off, kb + akb_off);
                ldmx4(a[mt][0], a[mt][1], a[mt][2], a[mt][3], addr);
            }
            uint32_t b[8][2];
            #pragma unroll
            for (int np = 0; np < 4; np++) {
                uint32_t addr = smb + tphys(qc + wc + np * 16 + brow_off, kb + bkb_off);
                uint32_t r0, r1, r2, r3;
                ldmx4(r0, r1, r2, r3, addr);
                b[np * 2][0] = r0; b[np * 2][1] = r1;
                b[np * 2 + 1][0] = r2; b[np * 2 + 1][1] = r3;
            }
            #pragma unroll
            for (int mt = 0; mt < 2; mt++)
                #pragma unroll
                for (int nt = 0; nt < 8; nt++)
                    mma16816(acc[mt][nt], a[mt][0], a[mt][1], a[mt][2], a[mt][3],
                             b[nt][0], b[nt][1]);
        }

        float qsum = 0.f;
        #pragma unroll
        for (int mt = 0; mt < 2; mt++) {
            int r0l = qr + wr + mt * 16 + lr;
            float sa0 = sq[r0l], sa1 = sq[r0l + 8];
            #pragma unroll
            for (int nt = 0; nt < 8; nt++) {
                int cl = qc + wc + nt * 8 + lc;
                float sb0 = sq[cl], sb1 = sq[cl + 1];
                float* c = acc[mt][nt];
                float d00 = sqrtf(fmaxf(sa0 + sb0 - 2.0f * c[0], 0.0f) + 1e-12f);
                float d01 = sqrtf(fmaxf(sa0 + sb1 - 2.0f * c[1], 0.0f) + 1e-12f);
                float d10 = sqrtf(fmaxf(sa1 + sb0 - 2.0f * c[2], 0.0f) + 1e-12f);
                float d11 = sqrtf(fmaxf(sa1 + sb1 - 2.0f * c[3], 0.0f) + 1e-12f);
                qsum += (d00 + d01) + (d10 + d11);
                __nv_bfloat162 p0 = __floats2bfloat162_rn(d00, d01);
                __nv_bfloat162 p1 = __floats2bfloat162_rn(d10, d11);
                *(uint32_t*)(Dslot + ((size_t)r0l << 8) + cl)       = *(uint32_t*)&p0;
                *(uint32_t*)(Dslot + ((size_t)(r0l + 8) << 8) + cl) = *(uint32_t*)&p1;
            }
        }
        tsum = fmaf(w, qsum, tsum);
    }

    #pragma unroll
    for (int off = 16; off > 0; off >>= 1)
        tsum += __shfl_down_sync(0xffffffffu, tsum, off);
    if (lane == 0) rsum[wid] = tsum;
    __syncthreads();
    if (tid == 0) {
        float tot = 0.f;
        #pragma unroll
        for (int w8 = 0; w8 < 8; w8++) tot += rsum[w8];
        g_sumD[s] = tot;
    }
}

// ---------------- hist inner: 12-bin two-center recurrence (single exp anchor) ----------------
struct HistCtx {
    unsigned long long sbin2, GA2, c16GA2, m2GA2, p8GA2, C2;
};
static __device__ __forceinline__ void hist_pair(const HistCtx& cx,
                                                 unsigned long long acc[NBINC],
                                                 float d0, float d1,
                                                 unsigned long long wv, bool weighted) {
    unsigned long long p = mul2(pk2(d0, d1), cx.sbin2);
    unsigned long long pg   = mul2(p, cx.GA2);
    unsigned long long arg0 = ffma2(pg, p, cx.c16GA2);
    unsigned long long rarg = ffma2(p, cx.m2GA2, cx.p8GA2);
    float a0l, a0h, rl, rh;
    up2(arg0, a0l, a0h); up2(rarg, rl, rh);
    unsigned long long t0 = pk2(ex2f(a0l), ex2f(a0h));
    unsigned long long rr = pk2(ex2f(rl), ex2f(rh));
    if (weighted) t0 = mul2(t0, wv);
    // t8 = t0 * rr^8 (exact algebraic identity)
    unsigned long long rr2 = mul2(rr, rr);
    unsigned long long rr4 = mul2(rr2, rr2);
    unsigned long long rr8 = mul2(rr4, rr4);
    unsigned long long t8  = mul2(t0, rr8);
    unsigned long long r2  = mul2(rr, cx.C2);

    acc[0] = add2(acc[0], t0);
    #pragma unroll
    for (int k = 1; k < 8; k++) {
        t0 = mul2(t0, rr);
        acc[k] = add2(acc[k], t0);
    }
    acc[8] = add2(acc[8], t8);
    #pragma unroll
    for (int k = 9; k < NBINC; k++) {
        t8 = mul2(t8, r2);
        acc[k] = add2(acc[k], t8);
    }
}

// ---------------- kernel 3: soft histogram ----------------
__global__ __launch_bounds__(256) void k_hist() {
    int bx = blockIdx.x;
    int s = bx >> 1, part = bx & 1;
    int tid = threadIdx.x;
    const uint4* Du4 = (const uint4*)(g_Dbf + ((size_t)s << 16));

    float mean = g_sumD[s] * (1.0f / 65536.0f);
    float sbin = 5.0f / (mean + 1e-8f);

    HistCtx cx;
    cx.sbin2  = pk2(sbin, sbin);
    cx.GA2    = pk2(GA, GA);
    cx.c16GA2 = pk2(-16.0f * GA, -16.0f * GA);
    cx.m2GA2  = pk2(-2.0f * GA, -2.0f * GA);
    cx.p8GA2  = pk2(8.0f * GA, 8.0f * GA);
    float Cs = ex2f(16.0f * GA);
    cx.C2 = pk2(Cs, Cs);

    unsigned long long acc[NBINC];
    #pragma unroll
    for (int k = 0; k < NBINC; k++) acc[k] = 0ULL;

    if (part == 0) {
        #pragma unroll 1
        for (int it = 0; it < 8; it++) {
            int i = it * 256 + tid;
            int r = i >> 4, u = (i & 15) + 16;
            uint4 v = Du4[(r << 5) + u];
            uint32_t pw[4] = {v.x, v.y, v.z, v.w};
            #pragma unroll
            for (int e = 0; e < 4; e++) {
                float2 f = __bfloat1622float2(*(__nv_bfloat162*)&pw[e]);
                hist_pair(cx, acc, f.x, f.y, 0ULL, false);
            }
        }
    } else {
        int h = tid & 63;
        int par = (tid >> 6) & 1;
        int quad = tid >> 7;
        int rowoff = quad << 7;
        int ucol = quad << 4;
        #pragma unroll 1
        for (int half = 0; half < 2; half++) {
            int row = half ? (127 - h) : h;
            #pragma unroll 1
            for (int c4 = par; c4 < 16; c4 += 2) {
                int j0 = c4 << 3;
                if (j0 + 7 <= row) continue;
                uint4 v = Du4[((rowoff + row) << 5) + ucol + c4];
                uint32_t pw[4] = {v.x, v.y, v.z, v.w};
                #pragma unroll
                for (int e = 0; e < 4; e++) {
                    int j = j0 + e * 2;
                    float2 f = __bfloat1622float2(*(__nv_bfloat162*)&pw[e]);
                    float wlo = (j     > row) ? 2.0f : 0.0f;
                    float whi = (j + 1 > row) ? 2.0f : 0.0f;
                    hist_pair(cx, acc, f.x, f.y, pk2(wlo, whi), true);
                }
            }
        }
    }

    __shared__ float hsm[8][NBINC];
    #pragma unroll
    for (int k = 0; k < NBINC; k++) {
        int ctr = (k < 8) ? 4 : 12;
        float sc = ex2f(GA * (float)((k - ctr) * (k - ctr)));
        float lo, hi;
        up2(acc[k], lo, hi);
        float v = (lo + hi) * sc;
        #pragma unroll
        for (int off = 16; off > 0; off >>= 1)
            v += __shfl_down_sync(0xffffffffu, v, off);
        if ((tid & 31) == 0) hsm[tid >> 5][k] = v;
    }
    __syncthreads();
    if (tid < KBINS) {
        float t = 0.f;
        if (tid < NBINC) {
            #pragma unroll
            for (int w8 = 0; w8 < 8; w8++) t += hsm[w8][tid];
            if (part == 0) t *= 2.0f;
        }
        g_hpart[(s * 2 + part) * KBINS + tid] = t;
    }
}

// ---------------- final reduction tail (noinline: keep k_ntxent regs low) ----------------
static __device__ __noinline__ void final_reduce(float* __restrict__ out, int t) {
    __shared__ float fred8[8];
    __shared__ float ftsave;
    int lane = t & 31, wrp = t >> 5;

    float v = 0.f;
    if (t < NG) {
        float h1[KBINS], h2[KBINS];
        float sA = 0.f, sB = 0.f;
        #pragma unroll
        for (int k = 0; k < KBINS; k++) {
            float dc = 256.0f * ex2f(GA * (float)(k * k));   // analytic diagonal
            float a = g_hpart[(t * 2) * KBINS + k] + g_hpart[(t * 2 + 1) * KBINS + k] + dc;
            float b = g_hpart[((t + NG) * 2) * KBINS + k] + g_hpart[((t + NG) * 2 + 1) * KBINS + k] + dc;
            h1[k] = a; h2[k] = b; sA += a; sB += b;
        }
        float iA = 1.f / (sA + 1e-8f), iB = 1.f / (sB + 1e-8f);
        float mm = 0.f;
        #pragma unroll
        for (int k = 0; k < KBINS; k++) {
            float d = h1[k] * iA - h2[k] * iB;
            mm += d * d;
        }
        v = mm * (1.0f / KBINS);
    }
    #pragma unroll
    for (int off = 16; off > 0; off >>= 1)
        v += __shfl_down_sync(0xffffffffu, v, off);
    if (lane == 0) fred8[wrp] = v;
    __syncthreads();
    if (t == 0) {
        float tot = 0.f;
        #pragma unroll
        for (int w8 = 0; w8 < 8; w8++) tot += fred8[w8];
        ftsave = tot;
    }
    __syncthreads();

    float r = g_rowloss[t];
    #pragma unroll
    for (int off = 16; off > 0; off >>= 1)
        r += __shfl_down_sync(0xffffffffu, r, off);
    __syncthreads();
    if (lane == 0) fred8[wrp] = r;
    __syncthreads();
    if (t == 0) {
        float tot = 0.f;
        #pragma unroll
        for (int w8 = 0; w8 < 8; w8++) tot += fred8[w8];
        float topo = ftsave * (1.0f / NG);
        float ntx  = tot * (1.0f / NSLOT);
        out[0] = LAMBDA * (topo + ntx);
    }
}

// ---------------- kernel 4: NT-Xent (one block per row) + fused final ----------------
__global__ __launch_bounds__(256) void k_ntxent(float* __restrict__ out) {
    __shared__ float4 zr4[32];
    __shared__ float sims[256];
    __shared__ float red8[8];
    __shared__ int   lastflag;

    int i = blockIdx.x;
    int t = threadIdx.x;
    int lane = t & 31, wrp = t >> 5;

    if (t < 32) zr4[t] = ((const float4*)(g_znR + (size_t)i * DF))[t];
    if (t == 0) lastflag = 0;
    __syncthreads();

    float acc = 0.f;
    #pragma unroll
    for (int k4 = 0; k4 < 32; k4++) {
        float4 b = g_znT4[k4 * NSLOT + t];
        float4 a = zr4[k4];
        acc = fmaf(a.x, b.x, fmaf(a.y, b.y, fmaf(a.z, b.z, fmaf(a.w, b.w, acc))));
    }
    float sim = acc * INV_TEMP;
    if (t == i) sim = -1e9f;
    sims[t] = sim;

    float m = sim;
    #pragma unroll
    for (int off = 16; off > 0; off >>= 1)
        m = fmaxf(m, __shfl_xor_sync(0xffffffffu, m, off));
    if (lane == 0) red8[wrp] = m;
    __syncthreads();
    float rmax = red8[0];
    #pragma unroll
    for (int w8 = 1; w8 < 8; w8++) rmax = fmaxf(rmax, red8[w8]);

    float e = __expf(sim - rmax);
    #pragma unroll
    for (int off = 16; off > 0; off >>= 1)
        e += __shfl_down_sync(0xffffffffu, e, off);
    __syncthreads();
    if (lane == 0) red8[wrp] = e;
    __syncthreads();
    if (t == 0) {
        float tot = 0.f;
        #pragma unroll
        for (int w8 = 0; w8 < 8; w8++) tot += red8[w8];
        int label = (i < NG) ? i + NG : i - NG;
        g_rowloss[i] = rmax + logf(tot) - sims[label];
        __threadfence();
        int old = atomicAdd(&g_ticket, 1);
        if (old == NSLOT - 1) lastflag = 1;
    }
    __syncthreads();
    if (!lastflag) return;

    final_reduce(out, t);
}

// ---------------- launcher ----------------
extern "C" void kernel_launch(void* const* d_in, const int* in_sizes, int n_in,
                              void* d_out, int out_size) {
    const float* H1 = (const float*)d_in[0];
    const float* H2 = (const float*)d_in[2];
    const float* z1 = (const float*)d_in[4];
    const float* z2 = (const float*)d_in[5];
    float* out = (float*)d_out;

    cudaFuncSetAttribute(k_gemm, cudaFuncAttributeMaxDynamicSharedMemorySize, 65536);

    k_znorm<<<32, 256>>>(z1, z2);
    k_gemm<<<NSLOT, 256, 65536>>>(H1, H2);
    k_hist<<<NSLOT * 2, 256>>>();
    k_ntxent<<<NSLOT, 256>>>(out);
}

// round 12
// speedup vs baseline: 1.0087x; 1.0087x over previous
#include <cuda_runtime.h>
#include <cuda_bf16.h>
#include <math.h>
#include <stdint.h>

// ---------------- problem constants ----------------
#define NG    128
#define NPG   256
#define DF    128
#define KBINS 16
#define NBINC 12               // computed bins (12..15 analytically ~0)
#define NSLOT 256

#define INV_TEMP 2.0f
#define LAMBDA   0.1f
#define GA (-0.82073318f)      // a*log2(e), a = -0.5/(0.9375^2)

// ---------------- device scratch ----------------
__device__ __nv_bfloat16 g_Dbf[(size_t)NSLOT * NPG * NPG];   // distances (3 of 4 quadrants)
__device__ float g_sumD[NSLOT];
__device__ float g_hpart[NSLOT * 2 * KBINS];
__device__ float g_rowloss[NSLOT];
__device__ float4 g_znT4[32 * NSLOT];      // [k4][row]
__device__ float g_znR[NSLOT * DF];
__device__ int   g_ticket;

// ---------------- helpers ----------------
static __device__ __forceinline__ uint32_t smem_u32(const void* p) {
    uint32_t a;
    asm("{ .reg .u64 t; cvta.to.shared.u64 t, %1; cvt.u32.u64 %0, t; }" : "=r"(a) : "l"(p));
    return a;
}
static __device__ __forceinline__ unsigned long long pk2(float lo, float hi) {
    unsigned long long r;
    asm("mov.b64 %0, {%1, %2};" : "=l"(r) : "r"(__float_as_uint(lo)), "r"(__float_as_uint(hi)));
    return r;
}
static __device__ __forceinline__ unsigned long long mul2(unsigned long long a, unsigned long long b) {
    unsigned long long r;
    asm("mul.rn.f32x2 %0, %1, %2;" : "=l"(r) : "l"(a), "l"(b));
    return r;
}
static __device__ __forceinline__ unsigned long long add2(unsigned long long a, unsigned long long b) {
    unsigned long long r;
    asm("add.rn.f32x2 %0, %1, %2;" : "=l"(r) : "l"(a), "l"(b));
    return r;
}
static __device__ __forceinline__ unsigned long long ffma2(unsigned long long a, unsigned long long b, unsigned long long c) {
    unsigned long long r;
    asm("fma.rn.f32x2 %0, %1, %2, %3;" : "=l"(r) : "l"(a), "l"(b), "l"(c));
    return r;
}
static __device__ __forceinline__ void up2(unsigned long long v, float& lo, float& hi) {
    unsigned ulo, uhi;
    asm("mov.b64 {%0, %1}, %2;" : "=r"(ulo), "=r"(uhi) : "l"(v));
    lo = __uint_as_float(ulo); hi = __uint_as_float(uhi);
}
static __device__ __forceinline__ float ex2f(float x) {
    float r; asm("ex2.approx.f32 %0, %1;" : "=f"(r) : "f"(x)); return r;
}
static __device__ __forceinline__ void ldmx4(uint32_t& r0, uint32_t& r1, uint32_t& r2, uint32_t& r3, uint32_t addr) {
    asm volatile("ldmatrix.sync.aligned.m8n8.x4.shared.b16 {%0,%1,%2,%3}, [%4];"
                 : "=r"(r0), "=r"(r1), "=r"(r2), "=r"(r3) : "r"(addr));
}
static __device__ __forceinline__ void mma16816(float* c, uint32_t a0, uint32_t a1, uint32_t a2, uint32_t a3,
                                                uint32_t b0, uint32_t b1) {
    asm volatile("mma.sync.aligned.m16n8k16.row.col.f32.bf16.bf16.f32 "
                 "{%0,%1,%2,%3}, {%4,%5,%6,%7}, {%8,%9}, {%0,%1,%2,%3};"
                 : "+f"(c[0]), "+f"(c[1]), "+f"(c[2]), "+f"(c[3])
                 : "r"(a0), "r"(a1), "r"(a2), "r"(a3), "r"(b0), "r"(b1));
}
static __device__ __forceinline__ uint32_t tphys(int row, int kbyte) {
    return (uint32_t)(row * 256 + ((((kbyte >> 4) ^ (row & 7)) << 4) | (kbyte & 15)));
}

// ---------------- kernel 1: znorm (also resets final ticket) ----------------
__global__ __launch_bounds__(256) void k_znorm(const float* __restrict__ z1,
                                               const float* __restrict__ z2) {
    if (blockIdx.x == 0 && threadIdx.x == 0) g_ticket = 0;
    int wid = threadIdx.x >> 5;
    int lane = threadIdx.x & 31;
    int row = blockIdx.x * 8 + wid;
    const float* zr = (row < NG) ? (z1 + (size_t)row * DF) : (z2 + (size_t)(row - NG) * DF);
    float4 v = ((const float4*)zr)[lane];
    float ss = v.x * v.x + v.y * v.y + v.z * v.z + v.w * v.w;
    #pragma unroll
    for (int off = 16; off > 0; off >>= 1)
        ss += __shfl_down_sync(0xffffffffu, ss, off);
    float inv = 1.0f / (sqrtf(__shfl_sync(0xffffffffu, ss, 0)) + 1e-8f);
    float4 o = make_float4(v.x * inv, v.y * inv, v.z * inv, v.w * inv);
    ((float4*)(g_znR + (size_t)row * DF))[lane] = o;
    g_znT4[lane * NSLOT + row] = o;
}

// ---------------- kernel 2: HMMA Gram + fused NT-Xent row ----------------
__global__ __launch_bounds__(256, 2) void k_gemm(const float* __restrict__ H1,
                                                 const float* __restrict__ H2) {
    extern __shared__ char smraw[];                 // A: 256x128 bf16 swizzled = 64KB
    __shared__ float sq[256], rsum[8];
    __shared__ float4 zr4[32];
    __shared__ float sims[256];
    __shared__ float red8[8];

    int s = blockIdx.x;
    int g = s & (NG - 1);
    const float* H = (s < NG ? H1 : H2) + (size_t)g * NPG * DF;
    int tid = threadIdx.x;
    int lane = tid & 31;
    int wid = tid >> 5;

    // ---- load H tile -> bf16 swizzled smem; sq from same bf16 values ----
    if (tid < 32) zr4[tid] = ((const float4*)(g_znR + (size_t)s * DF))[tid];
    #pragma unroll
    for (int it = 0; it < 16; it++) {
        int i = tid + it * 256;
        int row = i >> 4, u = i & 15;
        const float4* p = (const float4*)(H + (size_t)row * DF + u * 8);
        float4 v0 = p[0], v1 = p[1];
        __nv_bfloat162 h0 = __floats2bfloat162_rn(v0.x, v0.y);
        __nv_bfloat162 h1 = __floats2bfloat162_rn(v0.z, v0.w);
        __nv_bfloat162 h2 = __floats2bfloat162_rn(v1.x, v1.y);
        __nv_bfloat162 h3 = __floats2bfloat162_rn(v1.z, v1.w);
        uint4 st;
        st.x = *(uint32_t*)&h0; st.y = *(uint32_t*)&h1;
        st.z = *(uint32_t*)&h2; st.w = *(uint32_t*)&h3;
        *(uint4*)(smraw + tphys(row, u * 16)) = st;
        float2 f0 = __bfloat1622float2(h0), f1 = __bfloat1622float2(h1);
        float2 f2 = __bfloat1622float2(h2), f3 = __bfloat1622float2(h3);
        float ssq = f0.x * f0.x + f0.y * f0.y + f1.x * f1.x + f1.y * f1.y
                  + f2.x * f2.x + f2.y * f2.y + f3.x * f3.x + f3.y * f3.y;
        ssq += __shfl_down_sync(0xffffffffu, ssq, 8, 16);
        ssq += __shfl_down_sync(0xffffffffu, ssq, 4, 16);
        ssq += __shfl_down_sync(0xffffffffu, ssq, 2, 16);
        ssq += __shfl_down_sync(0xffffffffu, ssq, 1, 16);
        if ((lane & 15) == 0) sq[row] = ssq;
    }
    __syncthreads();

    // ---- fused NT-Xent: this block computes row s of the sim matrix ----
    {
        float acc = 0.f;
        #pragma unroll
        for (int k4 = 0; k4 < 32; k4++) {
            float4 b = g_znT4[k4 * NSLOT + tid];
            float4 a = zr4[k4];
            acc = fmaf(a.x, b.x, fmaf(a.y, b.y, fmaf(a.z, b.z, fmaf(a.w, b.w, acc))));
        }
        float sim = acc * INV_TEMP;
        if (tid == s) sim = -1e9f;
        sims[tid] = sim;

        float m = sim;
        #pragma unroll
        for (int off = 16; off > 0; off >>= 1)
            m = fmaxf(m, __shfl_xor_sync(0xffffffffu, m, off));
        if (lane == 0) red8[wid] = m;
        __syncthreads();
        float rmax = red8[0];
        #pragma unroll
        for (int w8 = 1; w8 < 8; w8++) rmax = fmaxf(rmax, red8[w8]);

        float e = __expf(sim - rmax);
        #pragma unroll
        for (int off = 16; off > 0; off >>= 1)
            e += __shfl_down_sync(0xffffffffu, e, off);
        __syncthreads();
        if (lane == 0) red8[wid] = e;
        __syncthreads();
        if (tid == 0) {
            float tot = 0.f;
            #pragma unroll
            for (int w8 = 0; w8 < 8; w8++) tot += red8[w8];
            int label = (s < NG) ? s + NG : s - NG;
            g_rowloss[s] = rmax + logf(tot) - sims[label];
        }
    }

    // ---- GEMM: warp tile 32x64; warps 4x2 over 128x128, 3 quadrants ----
    int wr = (wid >> 1) * 32;
    int wc = (wid & 1) * 64;
    uint32_t smb = smem_u32(smraw);

    int gA = lane >> 3;
    int arow_off = (gA & 1) * 8 + (lane & 7);
    int akb_off  = (gA >> 1) * 16;
    int brow_off = (gA >> 1) * 8 + (lane & 7);
    int bkb_off  = (gA & 1) * 16;
    int lr = lane >> 2;
    int lc = (lane & 3) * 2;
    __nv_bfloat16* Dslot = g_Dbf + ((size_t)s << 16);

    float tsum = 0.f;

    #pragma unroll 1
    for (int m = 0; m < 3; m++) {
        int qr = (m == 2) ? 128 : 0;
        int qc = (m >= 1) ? 128 : 0;
        float w = (m == 1) ? 2.0f : 1.0f;

        float acc[2][8][4];
        #pragma unroll
        for (int mt = 0; mt < 2; mt++)
            #pragma unroll
            for (int nt = 0; nt < 8; nt++)
                #pragma unroll
                for (int e = 0; e < 4; e++) acc[mt][nt][e] = 0.f;

        #pragma unroll 1
        for (int ks = 0; ks < 8; ks++) {
            int kb = ks * 32;
            uint32_t a[2][4];
            #pragma unroll
            for (int mt = 0; mt < 2; mt++) {
                uint32_t addr = smb + tphys(qr + wr + mt * 16 + arow_off, kb + akb_off);
                ldmx4(a[mt][0], a[mt][1], a[mt][2], a[mt][3], addr);
            }
            uint32_t b[8][2];
            #pragma unroll
            for (int np = 0; np < 4; np++) {
                uint32_t addr = smb + tphys(qc + wc + np * 16 + brow_off, kb + bkb_off);
                uint32_t r0, r1, r2, r3;
                ldmx4(r0, r1, r2, r3, addr);
                b[np * 2][0] = r0; b[np * 2][1] = r1;
                b[np * 2 + 1][0] = r2; b[np * 2 + 1][1] = r3;
            }
            #pragma unroll
            for (int mt = 0; mt < 2; mt++)
                #pragma unroll
                for (int nt = 0; nt < 8; nt++)
                    mma16816(acc[mt][nt], a[mt][0], a[mt][1], a[mt][2], a[mt][3],
                             b[nt][0], b[nt][1]);
        }

        float qsum = 0.f;
        #pragma unroll
        for (int mt = 0; mt < 2; mt++) {
            int r0l = qr + wr + mt * 16 + lr;
            float sa0 = sq[r0l], sa1 = sq[r0l + 8];
            #pragma unroll
            for (int nt = 0; nt < 8; nt++) {
                int cl = qc + wc + nt * 8 + lc;
                float sb0 = sq[cl], sb1 = sq[cl + 1];
                float* c = acc[mt][nt];
                float d00 = sqrtf(fmaxf(sa0 + sb0 - 2.0f * c[0], 0.0f) + 1e-12f);
                float d01 = sqrtf(fmaxf(sa0 + sb1 - 2.0f * c[1], 0.0f) + 1e-12f);
                float d10 = sqrtf(fmaxf(sa1 + sb0 - 2.0f * c[2], 0.0f) + 1e-12f);
                float d11 = sqrtf(fmaxf(sa1 + sb1 - 2.0f * c[3], 0.0f) + 1e-12f);
                qsum += (d00 + d01) + (d10 + d11);
                __nv_bfloat162 p0 = __floats2bfloat162_rn(d00, d01);
                __nv_bfloat162 p1 = __floats2bfloat162_rn(d10, d11);
                *(uint32_t*)(Dslot + ((size_t)r0l << 8) + cl)       = *(uint32_t*)&p0;
                *(uint32_t*)(Dslot + ((size_t)(r0l + 8) << 8) + cl) = *(uint32_t*)&p1;
            }
        }
        tsum = fmaf(w, qsum, tsum);
    }

    #pragma unroll
    for (int off = 16; off > 0; off >>= 1)
        tsum += __shfl_down_sync(0xffffffffu, tsum, off);
    if (lane == 0) rsum[wid] = tsum;
    __syncthreads();
    if (tid == 0) {
        float tot = 0.f;
        #pragma unroll
        for (int w8 = 0; w8 < 8; w8++) tot += rsum[w8];
        g_sumD[s] = tot;
    }
}

// ---------------- hist inner: 12-bin two-center recurrence (single exp anchor) ----------------
struct HistCtx {
    unsigned long long sbin2, GA2, c16GA2, m2GA2, p8GA2, C2;
};
static __device__ __forceinline__ void hist_pair(const HistCtx& cx,
                                                 unsigned long long acc[NBINC],
                                                 float d0, float d1,
                                                 unsigned long long wv, bool weighted) {
    unsigned long long p = mul2(pk2(d0, d1), cx.sbin2);
    unsigned long long pg   = mul2(p, cx.GA2);
    unsigned long long arg0 = ffma2(pg, p, cx.c16GA2);
    unsigned long long rarg = ffma2(p, cx.m2GA2, cx.p8GA2);
    float a0l, a0h, rl, rh;
    up2(arg0, a0l, a0h); up2(rarg, rl, rh);
    unsigned long long t0 = pk2(ex2f(a0l), ex2f(a0h));
    unsigned long long rr = pk2(ex2f(rl), ex2f(rh));
    if (weighted) t0 = mul2(t0, wv);
    unsigned long long rr2 = mul2(rr, rr);
    unsigned long long rr4 = mul2(rr2, rr2);
    unsigned long long rr8 = mul2(rr4, rr4);
    unsigned long long t8  = mul2(t0, rr8);
    unsigned long long r2  = mul2(rr, cx.C2);

    acc[0] = add2(acc[0], t0);
    #pragma unroll
    for (int k = 1; k < 8; k++) {
        t0 = mul2(t0, rr);
        acc[k] = add2(acc[k], t0);
    }
    acc[8] = add2(acc[8], t8);
    #pragma unroll
    for (int k = 9; k < NBINC; k++) {
        t8 = mul2(t8, r2);
        acc[k] = add2(acc[k], t8);
    }
}

// ---------------- final reduction tail ----------------
static __device__ __forceinline__ void final_reduce(float* __restrict__ out, int t) {
    __shared__ float fred8[8];
    __shared__ float ftsave;
    int lane = t & 31, wrp = t >> 5;

    float v = 0.f;
    if (t < NG) {
        float h1[KBINS], h2[KBINS];
        float sA = 0.f, sB = 0.f;
        #pragma unroll
        for (int k = 0; k < KBINS; k++) {
            float dc = 256.0f * ex2f(GA * (float)(k * k));   // analytic diagonal
            float a = g_hpart[(t * 2) * KBINS + k] + g_hpart[(t * 2 + 1) * KBINS + k] + dc;
            float b = g_hpart[((t + NG) * 2) * KBINS + k] + g_hpart[((t + NG) * 2 + 1) * KBINS + k] + dc;
            h1[k] = a; h2[k] = b; sA += a; sB += b;
        }
        float iA = 1.f / (sA + 1e-8f), iB = 1.f / (sB + 1e-8f);
        float mm = 0.f;
        #pragma unroll
        for (int k = 0; k < KBINS; k++) {
            float d = h1[k] * iA - h2[k] * iB;
            mm += d * d;
        }
        v = mm * (1.0f / KBINS);
    }
    #pragma unroll
    for (int off = 16; off > 0; off >>= 1)
        v += __shfl_down_sync(0xffffffffu, v, off);
    if (lane == 0) fred8[wrp] = v;
    __syncthreads();
    if (t == 0) {
        float tot = 0.f;
        #pragma unroll
        for (int w8 = 0; w8 < 8; w8++) tot += fred8[w8];
        ftsave = tot;
    }
    __syncthreads();

    float r = g_rowloss[t];
    #pragma unroll
    for (int off = 16; off > 0; off >>= 1)
        r += __shfl_down_sync(0xffffffffu, r, off);
    __syncthreads();
    if (lane == 0) fred8[wrp] = r;
    __syncthreads();
    if (t == 0) {
        float tot = 0.f;
        #pragma unroll
        for (int w8 = 0; w8 < 8; w8++) tot += fred8[w8];
        float topo = ftsave * (1.0f / NG);
        float ntx  = tot * (1.0f / NSLOT);
        out[0] = LAMBDA * (topo + ntx);
    }
}

// ---------------- kernel 3: soft histogram + fused final ----------------
__global__ __launch_bounds__(256) void k_hist(float* __restrict__ out) {
    __shared__ int lastflag;
    int bx = blockIdx.x;
    int s = bx >> 1, part = bx & 1;
    int tid = threadIdx.x;
    const uint4* Du4 = (const uint4*)(g_Dbf + ((size_t)s << 16));
    if (tid == 0) lastflag = 0;

    float mean = g_sumD[s] * (1.0f / 65536.0f);
    float sbin = 5.0f / (mean + 1e-8f);

    HistCtx cx;
    cx.sbin2  = pk2(sbin, sbin);
    cx.GA2    = pk2(GA, GA);
    cx.c16GA2 = pk2(-16.0f * GA, -16.0f * GA);
    cx.m2GA2  = pk2(-2.0f * GA, -2.0f * GA);
    cx.p8GA2  = pk2(8.0f * GA, 8.0f * GA);
    float Cs = ex2f(16.0f * GA);
    cx.C2 = pk2(Cs, Cs);

    unsigned long long acc[NBINC];
    #pragma unroll
    for (int k = 0; k < NBINC; k++) acc[k] = 0ULL;

    if (part == 0) {
        #pragma unroll 1
        for (int it = 0; it < 8; it++) {
            int i = it * 256 + tid;
            int r = i >> 4, u = (i & 15) + 16;
            uint4 v = Du4[(r << 5) + u];
            uint32_t pw[4] = {v.x, v.y, v.z, v.w};
            #pragma unroll
            for (int e = 0; e < 4; e++) {
                float2 f = __bfloat1622float2(*(__nv_bfloat162*)&pw[e]);
                hist_pair(cx, acc, f.x, f.y, 0ULL, false);
            }
        }
    } else {
        int h = tid & 63;
        int par = (tid >> 6) & 1;
        int quad = tid >> 7;
        int rowoff = quad << 7;
        int ucol = quad << 4;
        #pragma unroll 1
        for (int half = 0; half < 2; half++) {
            int row = half ? (127 - h) : h;
            #pragma unroll 1
            for (int c4 = par; c4 < 16; c4 += 2) {
                int j0 = c4 << 3;
                if (j0 + 7 <= row) continue;
                uint4 v = Du4[((rowoff + row) << 5) + ucol + c4];
                uint32_t pw[4] = {v.x, v.y, v.z, v.w};
                #pragma unroll
                for (int e = 0; e < 4; e++) {
                    int j = j0 + e * 2;
                    float2 f = __bfloat1622float2(*(__nv_bfloat162*)&pw[e]);
                    float wlo = (j     > row) ? 2.0f : 0.0f;
                    float whi = (j + 1 > row) ? 2.0f : 0.0f;
                    hist_pair(cx, acc, f.x, f.y, pk2(wlo, whi), true);
                }
            }
        }
    }

    __shared__ float hsm[8][NBINC];
    #pragma unroll
    for (int k = 0; k < NBINC; k++) {
        int ctr = (k < 8) ? 4 : 12;
        float sc = ex2f(GA * (float)((k - ctr) * (k - ctr)));
        float lo, hi;
        up2(acc[k], lo, hi);
        float v = (lo + hi) * sc;
        #pragma unroll
        for (int off = 16; off > 0; off >>= 1)
            v += __shfl_down_sync(0xffffffffu, v, off);
        if ((tid & 31) == 0) hsm[tid >> 5][k] = v;
    }
    __syncthreads();
    if (tid < KBINS) {
        float t = 0.f;
        if (tid < NBINC) {
            #pragma unroll
            for (int w8 = 0; w8 < 8; w8++) t += hsm[w8][tid];
            if (part == 0) t *= 2.0f;
        }
        g_hpart[(s * 2 + part) * KBINS + tid] = t;
    }
    if (tid == 0) {
        __threadfence();
        int old = atomicAdd(&g_ticket, 1);
        if (old == 2 * NSLOT - 1) lastflag = 1;
    }
    __syncthreads();
    if (!lastflag) return;

    final_reduce(out, tid);
}

// ---------------- launcher ----------------
extern "C" void kernel_launch(void* const* d_in, const int* in_sizes, int n_in,
                              void* d_out, int out_size) {
    const float* H1 = (const float*)d_in[0];
    const float* H2 = (const float*)d_in[2];
    const float* z1 = (const float*)d_in[4];
    const float* z2 = (const float*)d_in[5];
    float* out = (float*)d_out;

    cudaFuncSetAttribute(k_gemm, cudaFuncAttributeMaxDynamicSharedMemorySize, 65536);

    k_znorm<<<32, 256>>>(z1, z2);
    k_gemm<<<NSLOT, 256, 65536>>>(H1, H2);
    k_hist<<<NSLOT * 2, 256>>>(out);
}

// round 13
// speedup vs baseline: 1.0746x; 1.0653x over previous
#include <cuda_runtime.h>
#include <cuda_bf16.h>
#include <math.h>
#include <stdint.h>

// ---------------- problem constants ----------------
#define NG    128
#define NPG   256
#define DF    128
#define KBINS 16
#define NBINC 12               // computed bins (12..15 analytically ~0)
#define NSLOT 256

#define INV_TEMP 2.0f
#define LAMBDA   0.1f
#define GA (-0.82073318f)      // a*log2(e), a = -0.5/(0.9375^2)

// ---------------- device scratch ----------------
__device__ __nv_bfloat16 g_Dbf[(size_t)NSLOT * NPG * NPG];   // distances (3 of 4 quadrants)
__device__ float g_sumD[NSLOT];
__device__ float g_hpart[NSLOT * 2 * KBINS];
__device__ float g_rowloss[NSLOT];
__device__ float4 g_znT4[32 * NSLOT];      // [k4][row]
__device__ float g_znR[NSLOT * DF];
__device__ int   g_ticket;

// ---------------- helpers ----------------
static __device__ __forceinline__ uint32_t smem_u32(const void* p) {
    uint32_t a;
    asm("{ .reg .u64 t; cvta.to.shared.u64 t, %1; cvt.u32.u64 %0, t; }" : "=r"(a) : "l"(p));
    return a;
}
static __device__ __forceinline__ unsigned long long pk2(float lo, float hi) {
    unsigned long long r;
    asm("mov.b64 %0, {%1, %2};" : "=l"(r) : "r"(__float_as_uint(lo)), "r"(__float_as_uint(hi)));
    return r;
}
static __device__ __forceinline__ unsigned long long mul2(unsigned long long a, unsigned long long b) {
    unsigned long long r;
    asm("mul.rn.f32x2 %0, %1, %2;" : "=l"(r) : "l"(a), "l"(b));
    return r;
}
static __device__ __forceinline__ unsigned long long add2(unsigned long long a, unsigned long long b) {
    unsigned long long r;
    asm("add.rn.f32x2 %0, %1, %2;" : "=l"(r) : "l"(a), "l"(b));
    return r;
}
static __device__ __forceinline__ unsigned long long ffma2(unsigned long long a, unsigned long long b, unsigned long long c) {
    unsigned long long r;
    asm("fma.rn.f32x2 %0, %1, %2, %3;" : "=l"(r) : "l"(a), "l"(b), "l"(c));
    return r;
}
static __device__ __forceinline__ void up2(unsigned long long v, float& lo, float& hi) {
    unsigned ulo, uhi;
    asm("mov.b64 {%0, %1}, %2;" : "=r"(ulo), "=r"(uhi) : "l"(v));
    lo = __uint_as_float(ulo); hi = __uint_as_float(uhi);
}
static __device__ __forceinline__ float ex2f(float x) {
    float r; asm("ex2.approx.f32 %0, %1;" : "=f"(r) : "f"(x)); return r;
}
static __device__ __forceinline__ void ldmx4(uint32_t& r0, uint32_t& r1, uint32_t& r2, uint32_t& r3, uint32_t addr) {
    asm volatile("ldmatrix.sync.aligned.m8n8.x4.shared.b16 {%0,%1,%2,%3}, [%4];"
                 : "=r"(r0), "=r"(r1), "=r"(r2), "=r"(r3) : "r"(addr));
}
static __device__ __forceinline__ void mma16816(float* c, uint32_t a0, uint32_t a1, uint32_t a2, uint32_t a3,
                                                uint32_t b0, uint32_t b1) {
    asm volatile("mma.sync.aligned.m16n8k16.row.col.f32.bf16.bf16.f32 "
                 "{%0,%1,%2,%3}, {%4,%5,%6,%7}, {%8,%9}, {%0,%1,%2,%3};"
                 : "+f"(c[0]), "+f"(c[1]), "+f"(c[2]), "+f"(c[3])
                 : "r"(a0), "r"(a1), "r"(a2), "r"(a3), "r"(b0), "r"(b1));
}
static __device__ __forceinline__ uint32_t tphys(int row, int kbyte) {
    return (uint32_t)(row * 256 + ((((kbyte >> 4) ^ (row & 7)) << 4) | (kbyte & 15)));
}

// ---------------- kernel 1: HMMA Gram (+ znorm row s, ticket reset) ----------------
__global__ __launch_bounds__(256, 2) void k_gemm(const float* __restrict__ H1,
                                                 const float* __restrict__ H2,
                                                 const float* __restrict__ z1,
                                                 const float* __restrict__ z2) {
    extern __shared__ char smraw[];                 // A: 256x128 bf16 swizzled = 64KB
    __shared__ float sq[256], rsum[8];

    int s = blockIdx.x;
    int g = s & (NG - 1);
    const float* H = (s < NG ? H1 : H2) + (size_t)g * NPG * DF;
    int tid = threadIdx.x;
    int lane = tid & 31;
    int wid = tid >> 5;

    // ---- warp 0: normalize z row s (tiny; no pressure on MMA loop) ----
    if (wid == 0) {
        if (s == 0 && lane == 0) g_ticket = 0;
        const float* zr = (s < NG) ? (z1 + (size_t)s * DF) : (z2 + (size_t)(s - NG) * DF);
        float4 v = ((const float4*)zr)[lane];
        float ss = v.x * v.x + v.y * v.y + v.z * v.z + v.w * v.w;
        #pragma unroll
        for (int off = 16; off > 0; off >>= 1)
            ss += __shfl_down_sync(0xffffffffu, ss, off);
        float inv = 1.0f / (sqrtf(__shfl_sync(0xffffffffu, ss, 0)) + 1e-8f);
        float4 o = make_float4(v.x * inv, v.y * inv, v.z * inv, v.w * inv);
        ((float4*)(g_znR + (size_t)s * DF))[lane] = o;
        g_znT4[lane * NSLOT + s] = o;
    }

    // ---- load H tile -> bf16 swizzled smem; sq from same bf16 values ----
    #pragma unroll
    for (int it = 0; it < 16; it++) {
        int i = tid + it * 256;
        int row = i >> 4, u = i & 15;
        const float4* p = (const float4*)(H + (size_t)row * DF + u * 8);
        float4 v0 = p[0], v1 = p[1];
        __nv_bfloat162 h0 = __floats2bfloat162_rn(v0.x, v0.y);
        __nv_bfloat162 h1 = __floats2bfloat162_rn(v0.z, v0.w);
        __nv_bfloat162 h2 = __floats2bfloat162_rn(v1.x, v1.y);
        __nv_bfloat162 h3 = __floats2bfloat162_rn(v1.z, v1.w);
        uint4 st;
        st.x = *(uint32_t*)&h0; st.y = *(uint32_t*)&h1;
        st.z = *(uint32_t*)&h2; st.w = *(uint32_t*)&h3;
        *(uint4*)(smraw + tphys(row, u * 16)) = st;
        float2 f0 = __bfloat1622float2(h0), f1 = __bfloat1622float2(h1);
        float2 f2 = __bfloat1622float2(h2), f3 = __bfloat1622float2(h3);
        float ssq = f0.x * f0.x + f0.y * f0.y + f1.x * f1.x + f1.y * f1.y
                  + f2.x * f2.x + f2.y * f2.y + f3.x * f3.x + f3.y * f3.y;
        ssq += __shfl_down_sync(0xffffffffu, ssq, 8, 16);
        ssq += __shfl_down_sync(0xffffffffu, ssq, 4, 16);
        ssq += __shfl_down_sync(0xffffffffu, ssq, 2, 16);
        ssq += __shfl_down_sync(0xffffffffu, ssq, 1, 16);
        if ((lane & 15) == 0) sq[row] = ssq;
    }
    __syncthreads();

    // ---- GEMM: warp tile 32x64; warps 4x2 over 128x128, 3 quadrants ----
    int wr = (wid >> 1) * 32;
    int wc = (wid & 1) * 64;
    uint32_t smb = smem_u32(smraw);

    int gA = lane >> 3;
    int arow_off = (gA & 1) * 8 + (lane & 7);
    int akb_off  = (gA >> 1) * 16;
    int brow_off = (gA >> 1) * 8 + (lane & 7);
    int bkb_off  = (gA & 1) * 16;
    int lr = lane >> 2;
    int lc = (lane & 3) * 2;
    __nv_bfloat16* Dslot = g_Dbf + ((size_t)s << 16);

    float tsum = 0.f;

    #pragma unroll 1
    for (int m = 0; m < 3; m++) {
        int qr = (m == 2) ? 128 : 0;
        int qc = (m >= 1) ? 128 : 0;
        float w = (m == 1) ? 2.0f : 1.0f;

        float acc[2][8][4];
        #pragma unroll
        for (int mt = 0; mt < 2; mt++)
            #pragma unroll
            for (int nt = 0; nt < 8; nt++)
                #pragma unroll
                for (int e = 0; e < 4; e++) acc[mt][nt][e] = 0.f;

        #pragma unroll 1
        for (int ks = 0; ks < 8; ks++) {
            int kb = ks * 32;
            uint32_t a[2][4];
            #pragma unroll
            for (int mt = 0; mt < 2; mt++) {
                uint32_t addr = smb + tphys(qr + wr + mt * 16 + arow_off, kb + akb_off);
                ldmx4(a[mt][0], a[mt][1], a[mt][2], a[mt][3], addr);
            }
            uint32_t b[8][2];
            #pragma unroll
            for (int np = 0; np < 4; np++) {
                uint32_t addr = smb + tphys(qc + wc + np * 16 + brow_off, kb + bkb_off);
                uint32_t r0, r1, r2, r3;
                ldmx4(r0, r1, r2, r3, addr);
                b[np * 2][0] = r0; b[np * 2][1] = r1;
                b[np * 2 + 1][0] = r2; b[np * 2 + 1][1] = r3;
            }
            #pragma unroll
            for (int mt = 0; mt < 2; mt++)
                #pragma unroll
                for (int nt = 0; nt < 8; nt++)
                    mma16816(acc[mt][nt], a[mt][0], a[mt][1], a[mt][2], a[mt][3],
                             b[nt][0], b[nt][1]);
        }

        float qsum = 0.f;
        #pragma unroll
        for (int mt = 0; mt < 2; mt++) {
            int r0l = qr + wr + mt * 16 + lr;
            float sa0 = sq[r0l], sa1 = sq[r0l + 8];
            #pragma unroll
            for (int nt = 0; nt < 8; nt++) {
                int cl = qc + wc + nt * 8 + lc;
                float sb0 = sq[cl], sb1 = sq[cl + 1];
                float* c = acc[mt][nt];
                float d00 = sqrtf(fmaxf(sa0 + sb0 - 2.0f * c[0], 0.0f) + 1e-12f);
                float d01 = sqrtf(fmaxf(sa0 + sb1 - 2.0f * c[1], 0.0f) + 1e-12f);
                float d10 = sqrtf(fmaxf(sa1 + sb0 - 2.0f * c[2], 0.0f) + 1e-12f);
                float d11 = sqrtf(fmaxf(sa1 + sb1 - 2.0f * c[3], 0.0f) + 1e-12f);
                qsum += (d00 + d01) + (d10 + d11);
                __nv_bfloat162 p0 = __floats2bfloat162_rn(d00, d01);
                __nv_bfloat162 p1 = __floats2bfloat162_rn(d10, d11);
                *(uint32_t*)(Dslot + ((size_t)r0l << 8) + cl)       = *(uint32_t*)&p0;
                *(uint32_t*)(Dslot + ((size_t)(r0l + 8) << 8) + cl) = *(uint32_t*)&p1;
            }
        }
        tsum = fmaf(w, qsum, tsum);
    }

    #pragma unroll
    for (int off = 16; off > 0; off >>= 1)
        tsum += __shfl_down_sync(0xffffffffu, tsum, off);
    if (lane == 0) rsum[wid] = tsum;
    __syncthreads();
    if (tid == 0) {
        float tot = 0.f;
        #pragma unroll
        for (int w8 = 0; w8 < 8; w8++) tot += rsum[w8];
        g_sumD[s] = tot;
    }
}

// ---------------- hist inner: 12-bin two-center recurrence (single exp anchor) ----------------
struct HistCtx {
    unsigned long long sbin2, GA2, c16GA2, m2GA2, p8GA2, C2;
};
static __device__ __forceinline__ void hist_pair(const HistCtx& cx,
                                                 unsigned long long acc[NBINC],
                                                 float d0, float d1,
                                                 unsigned long long wv, bool weighted) {
    unsigned long long p = mul2(pk2(d0, d1), cx.sbin2);
    unsigned long long pg   = mul2(p, cx.GA2);
    unsigned long long arg0 = ffma2(pg, p, cx.c16GA2);
    unsigned long long rarg = ffma2(p, cx.m2GA2, cx.p8GA2);
    float a0l, a0h, rl, rh;
    up2(arg0, a0l, a0h); up2(rarg, rl, rh);
    unsigned long long t0 = pk2(ex2f(a0l), ex2f(a0h));
    unsigned long long rr = pk2(ex2f(rl), ex2f(rh));
    if (weighted) t0 = mul2(t0, wv);
    unsigned long long rr2 = mul2(rr, rr);
    unsigned long long rr4 = mul2(rr2, rr2);
    unsigned long long rr8 = mul2(rr4, rr4);
    unsigned long long t8  = mul2(t0, rr8);
    unsigned long long r2  = mul2(rr, cx.C2);

    acc[0] = add2(acc[0], t0);
    #pragma unroll
    for (int k = 1; k < 8; k++) {
        t0 = mul2(t0, rr);
        acc[k] = add2(acc[k], t0);
    }
    acc[8] = add2(acc[8], t8);
    #pragma unroll
    for (int k = 9; k < NBINC; k++) {
        t8 = mul2(t8, r2);
        acc[k] = add2(acc[k], t8);
    }
}

// ---------------- final reduction tail ----------------
static __device__ __forceinline__ void final_reduce(float* __restrict__ out, int t) {
    __shared__ float fred8[8];
    __shared__ float ftsave;
    int lane = t & 31, wrp = t >> 5;

    float v = 0.f;
    if (t < NG) {
        float h1[KBINS], h2[KBINS];
        float sA = 0.f, sB = 0.f;
        #pragma unroll
        for (int k = 0; k < KBINS; k++) {
            float dc = 256.0f * ex2f(GA * (float)(k * k));   // analytic diagonal
            float a = g_hpart[(t * 2) * KBINS + k] + g_hpart[(t * 2 + 1) * KBINS + k] + dc;
            float b = g_hpart[((t + NG) * 2) * KBINS + k] + g_hpart[((t + NG) * 2 + 1) * KBINS + k] + dc;
            h1[k] = a; h2[k] = b; sA += a; sB += b;
        }
        float iA = 1.f / (sA + 1e-8f), iB = 1.f / (sB + 1e-8f);
        float mm = 0.f;
        #pragma unroll
        for (int k = 0; k < KBINS; k++) {
            float d = h1[k] * iA - h2[k] * iB;
            mm += d * d;
        }
        v = mm * (1.0f / KBINS);
    }
    #pragma unroll
    for (int off = 16; off > 0; off >>= 1)
        v += __shfl_down_sync(0xffffffffu, v, off);
    if (lane == 0) fred8[wrp] = v;
    __syncthreads();
    if (t == 0) {
        float tot = 0.f;
        #pragma unroll
        for (int w8 = 0; w8 < 8; w8++) tot += fred8[w8];
        ftsave = tot;
    }
    __syncthreads();

    float r = g_rowloss[t];
    #pragma unroll
    for (int off = 16; off > 0; off >>= 1)
        r += __shfl_down_sync(0xffffffffu, r, off);
    __syncthreads();
    if (lane == 0) fred8[wrp] = r;
    __syncthreads();
    if (t == 0) {
        float tot = 0.f;
        #pragma unroll
        for (int w8 = 0; w8 < 8; w8++) tot += fred8[w8];
        float topo = ftsave * (1.0f / NG);
        float ntx  = tot * (1.0f / NSLOT);
        out[0] = LAMBDA * (topo + ntx);
    }
}

// ---------------- kernel 2: soft histogram + ntxent(part0) + fused final ----------------
__global__ __launch_bounds__(256) void k_hist(float* __restrict__ out) {
    __shared__ int lastflag;
    __shared__ float4 zr4[32];
    __shared__ float sims[256];
    __shared__ float red8n[8];

    int bx = blockIdx.x;
    int s = bx >> 1, part = bx & 1;
    int tid = threadIdx.x;
    int lane = tid & 31, wrp = tid >> 5;
    const uint4* Du4 = (const uint4*)(g_Dbf + ((size_t)s << 16));
    if (tid == 0) lastflag = 0;

    // ---- ntxent row s (part 0 blocks only) ----
    if (part == 0) {
        if (tid < 32) zr4[tid] = ((const float4*)(g_znR + (size_t)s * DF))[tid];
        __syncthreads();
        float acc = 0.f;
        #pragma unroll
        for (int k4 = 0; k4 < 32; k4++) {
            float4 b = g_znT4[k4 * NSLOT + tid];
            float4 a = zr4[k4];
            acc = fmaf(a.x, b.x, fmaf(a.y, b.y, fmaf(a.z, b.z, fmaf(a.w, b.w, acc))));
        }
        float sim = acc * INV_TEMP;
        if (tid == s) sim = -1e9f;
        sims[tid] = sim;

        float m = sim;
        #pragma unroll
        for (int off = 16; off > 0; off >>= 1)
            m = fmaxf(m, __shfl_xor_sync(0xffffffffu, m, off));
        if (lane == 0) red8n[wrp] = m;
        __syncthreads();
        float rmax = red8n[0];
        #pragma unroll
        for (int w8 = 1; w8 < 8; w8++) rmax = fmaxf(rmax, red8n[w8]);

        float e = __expf(sim - rmax);
        #pragma unroll
        for (int off = 16; off > 0; off >>= 1)
            e += __shfl_down_sync(0xffffffffu, e, off);
        __syncthreads();
        if (lane == 0) red8n[wrp] = e;
        __syncthreads();
        if (tid == 0) {
            float tot = 0.f;
            #pragma unroll
            for (int w8 = 0; w8 < 8; w8++) tot += red8n[w8];
            int label = (s < NG) ? s + NG : s - NG;
            g_rowloss[s] = rmax + logf(tot) - sims[label];
        }
    }

    // ---- histogram ----
    float mean = g_sumD[s] * (1.0f / 65536.0f);
    float sbin = 5.0f / (mean + 1e-8f);

    HistCtx cx;
    cx.sbin2  = pk2(sbin, sbin);
    cx.GA2    = pk2(GA, GA);
    cx.c16GA2 = pk2(-16.0f * GA, -16.0f * GA);
    cx.m2GA2  = pk2(-2.0f * GA, -2.0f * GA);
    cx.p8GA2  = pk2(8.0f * GA, 8.0f * GA);
    float Cs = ex2f(16.0f * GA);
    cx.C2 = pk2(Cs, Cs);

    unsigned long long acc[NBINC];
    #pragma unroll
    for (int k = 0; k < NBINC; k++) acc[k] = 0ULL;

    if (part == 0) {
        #pragma unroll 1
        for (int it = 0; it < 8; it++) {
            int i = it * 256 + tid;
            int r = i >> 4, u = (i & 15) + 16;
            uint4 v = Du4[(r << 5) + u];
            uint32_t pw[4] = {v.x, v.y, v.z, v.w};
            #pragma unroll
            for (int e = 0; e < 4; e++) {
                float2 f = __bfloat1622float2(*(__nv_bfloat162*)&pw[e]);
                hist_pair(cx, acc, f.x, f.y, 0ULL, false);
            }
        }
    } else {
        int h = tid & 63;
        int par = (tid >> 6) & 1;
        int quad = tid >> 7;
        int rowoff = quad << 7;
        int ucol = quad << 4;
        #pragma unroll 1
        for (int half = 0; half < 2; half++) {
            int row = half ? (127 - h) : h;
            #pragma unroll 1
            for (int c4 = par; c4 < 16; c4 += 2) {
                int j0 = c4 << 3;
                if (j0 + 7 <= row) continue;
                uint4 v = Du4[((rowoff + row) << 5) + ucol + c4];
                uint32_t pw[4] = {v.x, v.y, v.z, v.w};
                #pragma unroll
                for (int e = 0; e < 4; e++) {
                    int j = j0 + e * 2;
                    float2 f = __bfloat1622float2(*(__nv_bfloat162*)&pw[e]);
                    float wlo = (j     > row) ? 2.0f : 0.0f;
                    float whi = (j + 1 > row) ? 2.0f : 0.0f;
                    hist_pair(cx, acc, f.x, f.y, pk2(wlo, whi), true);
                }
            }
        }
    }

    __shared__ float hsm[8][NBINC];
    #pragma unroll
    for (int k = 0; k < NBINC; k++) {
        int ctr = (k < 8) ? 4 : 12;
        float sc = ex2f(GA * (float)((k - ctr) * (k - ctr)));
        float lo, hi;
        up2(acc[k], lo, hi);
        float v = (lo + hi) * sc;
        #pragma unroll
        for (int off = 16; off > 0; off >>= 1)
            v += __shfl_down_sync(0xffffffffu, v, off);
        if ((tid & 31) == 0) hsm[tid >> 5][k] = v;
    }
    __syncthreads();
    if (tid < KBINS) {
        float t = 0.f;
        if (tid < NBINC) {
            #pragma unroll
            for (int w8 = 0; w8 < 8; w8++) t += hsm[w8][tid];
            if (part == 0) t *= 2.0f;
        }
        g_hpart[(s * 2 + part) * KBINS + tid] = t;
    }
    if (tid == 0) {
        __threadfence();
        int old = atomicAdd(&g_ticket, 1);
        if (old == 2 * NSLOT - 1) lastflag = 1;
    }
    __syncthreads();
    if (!lastflag) return;

    final_reduce(out, tid);
}

// ---------------- launcher ----------------
extern "C" void kernel_launch(void* const* d_in, const int* in_sizes, int n_in,
                              void* d_out, int out_size) {
    const float* H1 = (const float*)d_in[0];
    const float* H2 = (const float*)d_in[2];
    const float* z1 = (const float*)d_in[4];
    const float* z2 = (const float*)d_in[5];
    float* out = (float*)d_out;

    cudaFuncSetAttribute(k_gemm, cudaFuncAttributeMaxDynamicSharedMemorySize, 65536);

    k_gemm<<<NSLOT, 256, 65536>>>(H1, H2, z1, z2);
    k_hist<<<NSLOT * 2, 256>>>(out);
}

// round 14
// speedup vs baseline: 1.1288x; 1.0505x over previous
#include <cuda_runtime.h>
#include <cuda_bf16.h>
#include <math.h>
#include <stdint.h>

// ---------------- problem constants ----------------
#define NG    128
#define NPG   256
#define DF    128
#define KBINS 16
#define NBINC 12               // computed bins (12..15 analytically ~0)
#define NSLOT 256

#define INV_TEMP 2.0f
#define LAMBDA   0.1f
#define GA (-0.82073318f)      // a*log2(e), a = -0.5/(0.9375^2)

// ---------------- device scratch ----------------
__device__ __nv_bfloat16 g_Dbf[(size_t)NSLOT * NPG * NPG];   // distances (3 of 4 quadrants)
__device__ float g_sumD[NSLOT];
__device__ float g_hpart[NSLOT * 3 * KBINS];
__device__ float g_rowloss[NSLOT];
__device__ float4 g_znT4[32 * NSLOT];      // [k4][row]
__device__ float g_znR[NSLOT * DF];
__device__ int   g_ticket;

// ---------------- helpers ----------------
static __device__ __forceinline__ uint32_t smem_u32(const void* p) {
    uint32_t a;
    asm("{ .reg .u64 t; cvta.to.shared.u64 t, %1; cvt.u32.u64 %0, t; }" : "=r"(a) : "l"(p));
    return a;
}
static __device__ __forceinline__ unsigned long long pk2(float lo, float hi) {
    unsigned long long r;
    asm("mov.b64 %0, {%1, %2};" : "=l"(r) : "r"(__float_as_uint(lo)), "r"(__float_as_uint(hi)));
    return r;
}
static __device__ __forceinline__ unsigned long long mul2(unsigned long long a, unsigned long long b) {
    unsigned long long r;
    asm("mul.rn.f32x2 %0, %1, %2;" : "=l"(r) : "l"(a), "l"(b));
    return r;
}
static __device__ __forceinline__ unsigned long long add2(unsigned long long a, unsigned long long b) {
    unsigned long long r;
    asm("add.rn.f32x2 %0, %1, %2;" : "=l"(r) : "l"(a), "l"(b));
    return r;
}
static __device__ __forceinline__ unsigned long long ffma2(unsigned long long a, unsigned long long b, unsigned long long c) {
    unsigned long long r;
    asm("fma.rn.f32x2 %0, %1, %2, %3;" : "=l"(r) : "l"(a), "l"(b), "l"(c));
    return r;
}
static __device__ __forceinline__ void up2(unsigned long long v, float& lo, float& hi) {
    unsigned ulo, uhi;
    asm("mov.b64 {%0, %1}, %2;" : "=r"(ulo), "=r"(uhi) : "l"(v));
    lo = __uint_as_float(ulo); hi = __uint_as_float(uhi);
}
static __device__ __forceinline__ float ex2f(float x) {
    float r; asm("ex2.approx.f32 %0, %1;" : "=f"(r) : "f"(x)); return r;
}
static __device__ __forceinline__ void ldmx4(uint32_t& r0, uint32_t& r1, uint32_t& r2, uint32_t& r3, uint32_t addr) {
    asm volatile("ldmatrix.sync.aligned.m8n8.x4.shared.b16 {%0,%1,%2,%3}, [%4];"
                 : "=r"(r0), "=r"(r1), "=r"(r2), "=r"(r3) : "r"(addr));
}
static __device__ __forceinline__ void mma16816(float* c, uint32_t a0, uint32_t a1, uint32_t a2, uint32_t a3,
                                                uint32_t b0, uint32_t b1) {
    asm volatile("mma.sync.aligned.m16n8k16.row.col.f32.bf16.bf16.f32 "
                 "{%0,%1,%2,%3}, {%4,%5,%6,%7}, {%8,%9}, {%0,%1,%2,%3};"
                 : "+f"(c[0]), "+f"(c[1]), "+f"(c[2]), "+f"(c[3])
                 : "r"(a0), "r"(a1), "r"(a2), "r"(a3), "r"(b0), "r"(b1));
}
static __device__ __forceinline__ uint32_t tphys(int row, int kbyte) {
    return (uint32_t)(row * 256 + ((((kbyte >> 4) ^ (row & 7)) << 4) | (kbyte & 15)));
}

// ---------------- kernel 1: HMMA Gram (+ znorm row s, ticket reset) ----------------
__global__ __launch_bounds__(256, 2) void k_gemm(const float* __restrict__ H1,
                                                 const float* __restrict__ H2,
                                                 const float* __restrict__ z1,
                                                 const float* __restrict__ z2) {
    extern __shared__ char smraw[];                 // A: 256x128 bf16 swizzled = 64KB
    __shared__ float sq[256], rsum[8];

    int s = blockIdx.x;
    int g = s & (NG - 1);
    const float* H = (s < NG ? H1 : H2) + (size_t)g * NPG * DF;
    int tid = threadIdx.x;
    int lane = tid & 31;
    int wid = tid >> 5;

    // ---- warp 0: normalize z row s (tiny; no pressure on MMA loop) ----
    if (wid == 0) {
        if (s == 0 && lane == 0) g_ticket = 0;
        const float* zr = (s < NG) ? (z1 + (size_t)s * DF) : (z2 + (size_t)(s - NG) * DF);
        float4 v = ((const float4*)zr)[lane];
        float ss = v.x * v.x + v.y * v.y + v.z * v.z + v.w * v.w;
        #pragma unroll
        for (int off = 16; off > 0; off >>= 1)
            ss += __shfl_down_sync(0xffffffffu, ss, off);
        float inv = 1.0f / (sqrtf(__shfl_sync(0xffffffffu, ss, 0)) + 1e-8f);
        float4 o = make_float4(v.x * inv, v.y * inv, v.z * inv, v.w * inv);
        ((float4*)(g_znR + (size_t)s * DF))[lane] = o;
        g_znT4[lane * NSLOT + s] = o;
    }

    // ---- load H tile -> bf16 swizzled smem; sq from same bf16 values ----
    #pragma unroll
    for (int it = 0; it < 16; it++) {
        int i = tid + it * 256;
        int row = i >> 4, u = i & 15;
        const float4* p = (const float4*)(H + (size_t)row * DF + u * 8);
        float4 v0 = p[0], v1 = p[1];
        __nv_bfloat162 h0 = __floats2bfloat162_rn(v0.x, v0.y);
        __nv_bfloat162 h1 = __floats2bfloat162_rn(v0.z, v0.w);
        __nv_bfloat162 h2 = __floats2bfloat162_rn(v1.x, v1.y);
        __nv_bfloat162 h3 = __floats2bfloat162_rn(v1.z, v1.w);
        uint4 st;
        st.x = *(uint32_t*)&h0; st.y = *(uint32_t*)&h1;
        st.z = *(uint32_t*)&h2; st.w = *(uint32_t*)&h3;
        *(uint4*)(smraw + tphys(row, u * 16)) = st;
        float2 f0 = __bfloat1622float2(h0), f1 = __bfloat1622float2(h1);
        float2 f2 = __bfloat1622float2(h2), f3 = __bfloat1622float2(h3);
        float ssq = f0.x * f0.x + f0.y * f0.y + f1.x * f1.x + f1.y * f1.y
                  + f2.x * f2.x + f2.y * f2.y + f3.x * f3.x + f3.y * f3.y;
        ssq += __shfl_down_sync(0xffffffffu, ssq, 8, 16);
        ssq += __shfl_down_sync(0xffffffffu, ssq, 4, 16);
        ssq += __shfl_down_sync(0xffffffffu, ssq, 2, 16);
        ssq += __shfl_down_sync(0xffffffffu, ssq, 1, 16);
        if ((lane & 15) == 0) sq[row] = ssq;
    }
    __syncthreads();

    // ---- GEMM: warp tile 32x64; warps 4x2 over 128x128, 3 quadrants ----
    int wr = (wid >> 1) * 32;
    int wc = (wid & 1) * 64;
    uint32_t smb = smem_u32(smraw);

    int gA = lane >> 3;
    int arow_off = (gA & 1) * 8 + (lane & 7);
    int akb_off  = (gA >> 1) * 16;
    int brow_off = (gA >> 1) * 8 + (lane & 7);
    int bkb_off  = (gA & 1) * 16;
    int lr = lane >> 2;
    int lc = (lane & 3) * 2;
    __nv_bfloat16* Dslot = g_Dbf + ((size_t)s << 16);

    float tsum = 0.f;

    #pragma unroll 1
    for (int m = 0; m < 3; m++) {
        int qr = (m == 2) ? 128 : 0;
        int qc = (m >= 1) ? 128 : 0;
        float w = (m == 1) ? 2.0f : 1.0f;

        float acc[2][8][4];
        #pragma unroll
        for (int mt = 0; mt < 2; mt++)
            #pragma unroll
            for (int nt = 0; nt < 8; nt++)
                #pragma unroll
                for (int e = 0; e < 4; e++) acc[mt][nt][e] = 0.f;

        #pragma unroll 1
        for (int ks = 0; ks < 8; ks++) {
            int kb = ks * 32;
            uint32_t a[2][4];
            #pragma unroll
            for (int mt = 0; mt < 2; mt++) {
                uint32_t addr = smb + tphys(qr + wr + mt * 16 + arow_off, kb + akb_off);
                ldmx4(a[mt][0], a[mt][1], a[mt][2], a[mt][3], addr);
            }
            uint32_t b[8][2];
            #pragma unroll
            for (int np = 0; np < 4; np++) {
                uint32_t addr = smb + tphys(qc + wc + np * 16 + brow_off, kb + bkb_off);
                uint32_t r0, r1, r2, r3;
                ldmx4(r0, r1, r2, r3, addr);
                b[np * 2][0] = r0; b[np * 2][1] = r1;
                b[np * 2 + 1][0] = r2; b[np * 2 + 1][1] = r3;
            }
            #pragma unroll
            for (int mt = 0; mt < 2; mt++)
                #pragma unroll
                for (int nt = 0; nt < 8; nt++)
                    mma16816(acc[mt][nt], a[mt][0], a[mt][1], a[mt][2], a[mt][3],
                             b[nt][0], b[nt][1]);
        }

        float qsum = 0.f;
        #pragma unroll
        for (int mt = 0; mt < 2; mt++) {
            int r0l = qr + wr + mt * 16 + lr;
            float sa0 = sq[r0l], sa1 = sq[r0l + 8];
            #pragma unroll
            for (int nt = 0; nt < 8; nt++) {
                int cl = qc + wc + nt * 8 + lc;
                float sb0 = sq[cl], sb1 = sq[cl + 1];
                float* c = acc[mt][nt];
                float d00 = sqrtf(fmaxf(sa0 + sb0 - 2.0f * c[0], 0.0f) + 1e-12f);
                float d01 = sqrtf(fmaxf(sa0 + sb1 - 2.0f * c[1], 0.0f) + 1e-12f);
                float d10 = sqrtf(fmaxf(sa1 + sb0 - 2.0f * c[2], 0.0f) + 1e-12f);
                float d11 = sqrtf(fmaxf(sa1 + sb1 - 2.0f * c[3], 0.0f) + 1e-12f);
                qsum += (d00 + d01) + (d10 + d11);
                __nv_bfloat162 p0 = __floats2bfloat162_rn(d00, d01);
                __nv_bfloat162 p1 = __floats2bfloat162_rn(d10, d11);
                *(uint32_t*)(Dslot + ((size_t)r0l << 8) + cl)       = *(uint32_t*)&p0;
                *(uint32_t*)(Dslot + ((size_t)(r0l + 8) << 8) + cl) = *(uint32_t*)&p1;
            }
        }
        tsum = fmaf(w, qsum, tsum);
    }

    #pragma unroll
    for (int off = 16; off > 0; off >>= 1)
        tsum += __shfl_down_sync(0xffffffffu, tsum, off);
    if (lane == 0) rsum[wid] = tsum;
    __syncthreads();
    if (tid == 0) {
        float tot = 0.f;
        #pragma unroll
        for (int w8 = 0; w8 < 8; w8++) tot += rsum[w8];
        g_sumD[s] = tot;
    }
}

// ---------------- hist inner: 12-bin ffma2 power-tree ----------------
struct HistCtx {
    unsigned long long sbin2, GA2, c16GA2, m2GA2, p8GA2, C2;
};
static __device__ __forceinline__ void hist_pair(const HistCtx& cx,
                                                 unsigned long long acc[NBINC],
                                                 float d0, float d1,
                                                 unsigned long long wv, bool weighted) {
    unsigned long long p = mul2(pk2(d0, d1), cx.sbin2);
    unsigned long long pg   = mul2(p, cx.GA2);
    unsigned long long arg0 = ffma2(pg, p, cx.c16GA2);     // GA p^2 - 16GA
    unsigned long long rarg = ffma2(p, cx.m2GA2, cx.p8GA2); // -2GA p + 8GA
    float a0l, a0h, rl, rh;
    up2(arg0, a0l, a0h); up2(rarg, rl, rh);
    unsigned long long t0 = pk2(ex2f(a0l), ex2f(a0h));
    unsigned long long rr = pk2(ex2f(rl), ex2f(rh));
    if (weighted) t0 = mul2(t0, wv);

    unsigned long long rr2 = mul2(rr, rr);
    unsigned long long rr4 = mul2(rr2, rr2);
    unsigned long long t1  = mul2(t0, rr);
    unsigned long long t2  = mul2(t0, rr2);
    unsigned long long t3  = mul2(t1, rr2);

    acc[0] = add2(acc[0], t0);
    acc[1] = add2(acc[1], t1);
    acc[2] = add2(acc[2], t2);
    acc[3] = add2(acc[3], t3);
    acc[4] = ffma2(t0, rr4, acc[4]);
    acc[5] = ffma2(t1, rr4, acc[5]);
    acc[6] = ffma2(t2, rr4, acc[6]);
    acc[7] = ffma2(t3, rr4, acc[7]);

    unsigned long long rr8 = mul2(rr4, rr4);
    unsigned long long t8  = mul2(t0, rr8);
    unsigned long long rC  = mul2(rr, cx.C2);
    unsigned long long rC2 = mul2(rC, rC);
    unsigned long long rC3 = mul2(rC2, rC);

    acc[8]  = add2(acc[8], t8);
    acc[9]  = ffma2(t8, rC,  acc[9]);
    acc[10] = ffma2(t8, rC2, acc[10]);
    acc[11] = ffma2(t8, rC3, acc[11]);
}

// ---------------- final reduction tail ----------------
static __device__ __forceinline__ void final_reduce(float* __restrict__ out, int t) {
    __shared__ float fred8[8];
    __shared__ float ftsave;
    int lane = t & 31, wrp = t >> 5;

    float v = 0.f;
    if (t < NG) {
        float h1[KBINS], h2[KBINS];
        float sA = 0.f, sB = 0.f;
        #pragma unroll
        for (int k = 0; k < KBINS; k++) {
            float dc = 256.0f * ex2f(GA * (float)(k * k));   // analytic diagonal
            float a = dc, b = dc;
            #pragma unroll
            for (int p = 0; p < 3; p++) {
                a += g_hpart[(t * 3 + p) * KBINS + k];
                b += g_hpart[((t + NG) * 3 + p) * KBINS + k];
            }
            h1[k] = a; h2[k] = b; sA += a; sB += b;
        }
        float iA = 1.f / (sA + 1e-8f), iB = 1.f / (sB + 1e-8f);
        float mm = 0.f;
        #pragma unroll
        for (int k = 0; k < KBINS; k++) {
            float d = h1[k] * iA - h2[k] * iB;
            mm += d * d;
        }
        v = mm * (1.0f / KBINS);
    }
    #pragma unroll
    for (int off = 16; off > 0; off >>= 1)
        v += __shfl_down_sync(0xffffffffu, v, off);
    if (lane == 0) fred8[wrp] = v;
    __syncthreads();
    if (t == 0) {
        float tot = 0.f;
        #pragma unroll
        for (int w8 = 0; w8 < 8; w8++) tot += fred8[w8];
        ftsave = tot;
    }
    __syncthreads();

    float r = g_rowloss[t];
    #pragma unroll
    for (int off = 16; off > 0; off >>= 1)
        r += __shfl_down_sync(0xffffffffu, r, off);
    __syncthreads();
    if (lane == 0) fred8[wrp] = r;
    __syncthreads();
    if (t == 0) {
        float tot = 0.f;
        #pragma unroll
        for (int w8 = 0; w8 < 8; w8++) tot += fred8[w8];
        float topo = ftsave * (1.0f / NG);
        float ntx  = tot * (1.0f / NSLOT);
        out[0] = LAMBDA * (topo + ntx);
    }
}

// ---------------- kernel 2: soft histogram (3 parts/slot) + ntxent(part0) + final ----------------
__global__ __launch_bounds__(256) void k_hist(float* __restrict__ out) {
    __shared__ int lastflag;
    __shared__ float4 zr4[32];
    __shared__ float sims[256];
    __shared__ float red8n[8];

    int bx = blockIdx.x;
    int s = bx / 3, part = bx - s * 3;
    int tid = threadIdx.x;
    int lane = tid & 31, wrp = tid >> 5;
    const uint4* Du4 = (const uint4*)(g_Dbf + ((size_t)s << 16));
    if (tid == 0) lastflag = 0;

    // ---- ntxent row s (part 0 blocks only) ----
    if (part == 0) {
        if (tid < 32) zr4[tid] = ((const float4*)(g_znR + (size_t)s * DF))[tid];
        __syncthreads();
        float acc = 0.f;
        #pragma unroll
        for (int k4 = 0; k4 < 32; k4++) {
            float4 b = g_znT4[k4 * NSLOT + tid];
            float4 a = zr4[k4];
            acc = fmaf(a.x, b.x, fmaf(a.y, b.y, fmaf(a.z, b.z, fmaf(a.w, b.w, acc))));
        }
        float sim = acc * INV_TEMP;
        if (tid == s) sim = -1e9f;
        sims[tid] = sim;

        float m = sim;
        #pragma unroll
        for (int off = 16; off > 0; off >>= 1)
            m = fmaxf(m, __shfl_xor_sync(0xffffffffu, m, off));
        if (lane == 0) red8n[wrp] = m;
        __syncthreads();
        float rmax = red8n[0];
        #pragma unroll
        for (int w8 = 1; w8 < 8; w8++) rmax = fmaxf(rmax, red8n[w8]);

        float e = __expf(sim - rmax);
        #pragma unroll
        for (int off = 16; off > 0; off >>= 1)
            e += __shfl_down_sync(0xffffffffu, e, off);
        __syncthreads();
        if (lane == 0) red8n[wrp] = e;
        __syncthreads();
        if (tid == 0) {
            float tot = 0.f;
            #pragma unroll
            for (int w8 = 0; w8 < 8; w8++) tot += red8n[w8];
            int label = (s < NG) ? s + NG : s - NG;
            g_rowloss[s] = rmax + logf(tot) - sims[label];
        }
    }

    // ---- histogram ----
    float mean = g_sumD[s] * (1.0f / 65536.0f);
    float sbin = 5.0f / (mean + 1e-8f);

    HistCtx cx;
    cx.sbin2  = pk2(sbin, sbin);
    cx.GA2    = pk2(GA, GA);
    cx.c16GA2 = pk2(-16.0f * GA, -16.0f * GA);
    cx.m2GA2  = pk2(-2.0f * GA, -2.0f * GA);
    cx.p8GA2  = pk2(8.0f * GA, 8.0f * GA);
    float Cs = ex2f(16.0f * GA);
    cx.C2 = pk2(Cs, Cs);

    unsigned long long acc[NBINC];
    #pragma unroll
    for (int k = 0; k < NBINC; k++) acc[k] = 0ULL;

    if (part == 0) {
        // cross quadrant rows 0..127, cols 128..255
        #pragma unroll 1
        for (int it = 0; it < 8; it++) {
            int i = it * 256 + tid;
            int r = i >> 4, u = (i & 15) + 16;
            uint4 v = Du4[(r << 5) + u];
            uint32_t pw[4] = {v.x, v.y, v.z, v.w};
            #pragma unroll
            for (int e = 0; e < 4; e++) {
                float2 f = __bfloat1622float2(*(__nv_bfloat162*)&pw[e]);
                hist_pair(cx, acc, f.x, f.y, 0ULL, false);
            }
        }
    } else {
        // strict-upper triangle of diag quadrant (part-1 -> quad 0, part-2 -> quad 1)
        int quad = part - 1;
        int rowoff = quad << 7;
        int ucol = quad << 4;
        int h = tid & 63;
        int par4 = tid >> 6;          // 0..3
        #pragma unroll 1
        for (int half = 0; half < 2; half++) {
            int row = half ? (127 - h) : h;
            #pragma unroll 1
            for (int c4 = par4; c4 < 16; c4 += 4) {
                int j0 = c4 << 3;
                if (j0 + 7 <= row) continue;
                uint4 v = Du4[((rowoff + row) << 5) + ucol + c4];
                uint32_t pw[4] = {v.x, v.y, v.z, v.w};
                #pragma unroll
                for (int e = 0; e < 4; e++) {
                    int j = j0 + e * 2;
                    float2 f = __bfloat1622float2(*(__nv_bfloat162*)&pw[e]);
                    float wlo = (j     > row) ? 2.0f : 0.0f;
                    float whi = (j + 1 > row) ? 2.0f : 0.0f;
                    hist_pair(cx, acc, f.x, f.y, pk2(wlo, whi), true);
                }
            }
        }
    }

    __shared__ float hsm[8][NBINC];
    #pragma unroll
    for (int k = 0; k < NBINC; k++) {
        int ctr = (k < 8) ? 4 : 12;
        float sc = ex2f(GA * (float)((k - ctr) * (k - ctr)));
        float lo, hi;
        up2(acc[k], lo, hi);
        float v = (lo + hi) * sc;
        #pragma unroll
        for (int off = 16; off > 0; off >>= 1)
            v += __shfl_down_sync(0xffffffffu, v, off);
        if ((tid & 31) == 0) hsm[tid >> 5][k] = v;
    }
    __syncthreads();
    if (tid < KBINS) {
        float t = 0.f;
        if (tid < NBINC) {
            #pragma unroll
            for (int w8 = 0; w8 < 8; w8++) t += hsm[w8][tid];
            if (part == 0) t *= 2.0f;
        }
        g_hpart[(s * 3 + part) * KBINS + tid] = t;
    }
    if (tid == 0) {
        __threadfence();
        int old = atomicAdd(&g_ticket, 1);
        if (old == 3 * NSLOT - 1) lastflag = 1;
    }
    __syncthreads();
    if (!lastflag) return;

    final_reduce(out, tid);
}

// ---------------- launcher ----------------
extern "C" void kernel_launch(void* const* d_in, const int* in_sizes, int n_in,
                              void* d_out, int out_size) {
    const float* H1 = (const float*)d_in[0];
    const float* H2 = (const float*)d_in[2];
    const float* z1 = (const float*)d_in[4];
    const float* z2 = (const float*)d_in[5];
    float* out = (float*)d_out;

    cudaFuncSetAttribute(k_gemm, cudaFuncAttributeMaxDynamicSharedMemorySize, 65536);

    k_gemm<<<NSLOT, 256, 65536>>>(H1, H2, z1, z2);
    k_hist<<<NSLOT * 3, 256>>>(out);
}

// round 15
// speedup vs baseline: 1.1697x; 1.0362x over previous
#include <cuda_runtime.h>
#include <cuda_bf16.h>
#include <math.h>
#include <stdint.h>

// ---------------- problem constants ----------------
#define NG    128
#define NPG   256
#define DF    128
#define KBINS 16
#define NBINC 12               // computed bins (12..15 analytically ~0)
#define NSLOT 256

#define INV_TEMP 2.0f
#define LAMBDA   0.1f
#define GA (-0.82073318f)      // a*log2(e), a = -0.5/(0.9375^2)

// ---------------- device scratch ----------------
__device__ __nv_bfloat16 g_Dbf[(size_t)NSLOT * NPG * NPG];   // distances (3 of 4 quadrants)
__device__ float g_sumD[NSLOT];
__device__ float g_hpart[NSLOT * 3 * KBINS];
__device__ float g_rowloss[NSLOT];
__device__ float4 g_znT4[32 * NSLOT];      // [k4][row]
__device__ float g_znR[NSLOT * DF];
__device__ int   g_ticket;

// ---------------- helpers ----------------
static __device__ __forceinline__ uint32_t smem_u32(const void* p) {
    uint32_t a;
    asm("{ .reg .u64 t; cvta.to.shared.u64 t, %1; cvt.u32.u64 %0, t; }" : "=r"(a) : "l"(p));
    return a;
}
static __device__ __forceinline__ unsigned long long pk2(float lo, float hi) {
    unsigned long long r;
    asm("mov.b64 %0, {%1, %2};" : "=l"(r) : "r"(__float_as_uint(lo)), "r"(__float_as_uint(hi)));
    return r;
}
static __device__ __forceinline__ unsigned long long mul2(unsigned long long a, unsigned long long b) {
    unsigned long long r;
    asm("mul.rn.f32x2 %0, %1, %2;" : "=l"(r) : "l"(a), "l"(b));
    return r;
}
static __device__ __forceinline__ unsigned long long add2(unsigned long long a, unsigned long long b) {
    unsigned long long r;
    asm("add.rn.f32x2 %0, %1, %2;" : "=l"(r) : "l"(a), "l"(b));
    return r;
}
static __device__ __forceinline__ unsigned long long ffma2(unsigned long long a, unsigned long long b, unsigned long long c) {
    unsigned long long r;
    asm("fma.rn.f32x2 %0, %1, %2, %3;" : "=l"(r) : "l"(a), "l"(b), "l"(c));
    return r;
}
static __device__ __forceinline__ void up2(unsigned long long v, float& lo, float& hi) {
    unsigned ulo, uhi;
    asm("mov.b64 {%0, %1}, %2;" : "=r"(ulo), "=r"(uhi) : "l"(v));
    lo = __uint_as_float(ulo); hi = __uint_as_float(uhi);
}
static __device__ __forceinline__ float ex2f(float x) {
    float r; asm("ex2.approx.f32 %0, %1;" : "=f"(r) : "f"(x)); return r;
}
static __device__ __forceinline__ void ldmx4(uint32_t& r0, uint32_t& r1, uint32_t& r2, uint32_t& r3, uint32_t addr) {
    asm volatile("ldmatrix.sync.aligned.m8n8.x4.shared.b16 {%0,%1,%2,%3}, [%4];"
                 : "=r"(r0), "=r"(r1), "=r"(r2), "=r"(r3) : "r"(addr));
}
static __device__ __forceinline__ void mma16816(float* c, uint32_t a0, uint32_t a1, uint32_t a2, uint32_t a3,
                                                uint32_t b0, uint32_t b1) {
    asm volatile("mma.sync.aligned.m16n8k16.row.col.f32.bf16.bf16.f32 "
                 "{%0,%1,%2,%3}, {%4,%5,%6,%7}, {%8,%9}, {%0,%1,%2,%3};"
                 : "+f"(c[0]), "+f"(c[1]), "+f"(c[2]), "+f"(c[3])
                 : "r"(a0), "r"(a1), "r"(a2), "r"(a3), "r"(b0), "r"(b1));
}
static __device__ __forceinline__ uint32_t tphys(int row, int kbyte) {
    return (uint32_t)(row * 256 + ((((kbyte >> 4) ^ (row & 7)) << 4) | (kbyte & 15)));
}

// ---------------- kernel 1: HMMA Gram (+ znorm row s, ticket reset) ----------------
__global__ __launch_bounds__(256, 2) void k_gemm(const float* __restrict__ H1,
                                                 const float* __restrict__ H2,
                                                 const float* __restrict__ z1,
                                                 const float* __restrict__ z2) {
    extern __shared__ char smraw[];                 // A: 256x128 bf16 swizzled = 64KB
    __shared__ float sq[256], rsum[8];

    int s = blockIdx.x;
    int g = s & (NG - 1);
    const float* H = (s < NG ? H1 : H2) + (size_t)g * NPG * DF;
    int tid = threadIdx.x;
    int lane = tid & 31;
    int wid = tid >> 5;

    // ---- warp 0: normalize z row s ----
    if (wid == 0) {
        if (s == 0 && lane == 0) g_ticket = 0;
        const float* zr = (s < NG) ? (z1 + (size_t)s * DF) : (z2 + (size_t)(s - NG) * DF);
        float4 v = ((const float4*)zr)[lane];
        float ss = v.x * v.x + v.y * v.y + v.z * v.z + v.w * v.w;
        #pragma unroll
        for (int off = 16; off > 0; off >>= 1)
            ss += __shfl_down_sync(0xffffffffu, ss, off);
        float inv = 1.0f / (sqrtf(__shfl_sync(0xffffffffu, ss, 0)) + 1e-8f);
        float4 o = make_float4(v.x * inv, v.y * inv, v.z * inv, v.w * inv);
        ((float4*)(g_znR + (size_t)s * DF))[lane] = o;
        g_znT4[lane * NSLOT + s] = o;
    }

    // ---- load H tile -> bf16 swizzled smem; sq from same bf16 values ----
    #pragma unroll
    for (int it = 0; it < 16; it++) {
        int i = tid + it * 256;
        int row = i >> 4, u = i & 15;
        const float4* p = (const float4*)(H + (size_t)row * DF + u * 8);
        float4 v0 = p[0], v1 = p[1];
        __nv_bfloat162 h0 = __floats2bfloat162_rn(v0.x, v0.y);
        __nv_bfloat162 h1 = __floats2bfloat162_rn(v0.z, v0.w);
        __nv_bfloat162 h2 = __floats2bfloat162_rn(v1.x, v1.y);
        __nv_bfloat162 h3 = __floats2bfloat162_rn(v1.z, v1.w);
        uint4 st;
        st.x = *(uint32_t*)&h0; st.y = *(uint32_t*)&h1;
        st.z = *(uint32_t*)&h2; st.w = *(uint32_t*)&h3;
        *(uint4*)(smraw + tphys(row, u * 16)) = st;
        float2 f0 = __bfloat1622float2(h0), f1 = __bfloat1622float2(h1);
        float2 f2 = __bfloat1622float2(h2), f3 = __bfloat1622float2(h3);
        float ssq = f0.x * f0.x + f0.y * f0.y + f1.x * f1.x + f1.y * f1.y
                  + f2.x * f2.x + f2.y * f2.y + f3.x * f3.x + f3.y * f3.y;
        ssq += __shfl_down_sync(0xffffffffu, ssq, 8, 16);
        ssq += __shfl_down_sync(0xffffffffu, ssq, 4, 16);
        ssq += __shfl_down_sync(0xffffffffu, ssq, 2, 16);
        ssq += __shfl_down_sync(0xffffffffu, ssq, 1, 16);
        if ((lane & 15) == 0) sq[row] = ssq;
    }
    __syncthreads();

    // ---- GEMM: warp tile 32x64; warps 4x2 over 128x128, 3 quadrants ----
    int wr = (wid >> 1) * 32;
    int wc = (wid & 1) * 64;
    uint32_t smb = smem_u32(smraw);

    int gA = lane >> 3;
    int arow_off = (gA & 1) * 8 + (lane & 7);
    int akb_off  = (gA >> 1) * 16;
    int brow_off = (gA >> 1) * 8 + (lane & 7);
    int bkb_off  = (gA & 1) * 16;
    int lr = lane >> 2;
    int lc = (lane & 3) * 2;
    __nv_bfloat16* Dslot = g_Dbf + ((size_t)s << 16);

    float tsum = 0.f;

    #pragma unroll 1
    for (int m = 0; m < 3; m++) {
        int qr = (m == 2) ? 128 : 0;
        int qc = (m >= 1) ? 128 : 0;
        float w = (m == 1) ? 2.0f : 1.0f;

        float acc[2][8][4];
        #pragma unroll
        for (int mt = 0; mt < 2; mt++)
            #pragma unroll
            for (int nt = 0; nt < 8; nt++)
                #pragma unroll
                for (int e = 0; e < 4; e++) acc[mt][nt][e] = 0.f;

        #pragma unroll 1
        for (int ks = 0; ks < 8; ks++) {
            int kb = ks * 32;
            uint32_t a[2][4];
            #pragma unroll
            for (int mt = 0; mt < 2; mt++) {
                uint32_t addr = smb + tphys(qr + wr + mt * 16 + arow_off, kb + akb_off);
                ldmx4(a[mt][0], a[mt][1], a[mt][2], a[mt][3], addr);
            }
            uint32_t b[8][2];
            #pragma unroll
            for (int np = 0; np < 4; np++) {
                uint32_t addr = smb + tphys(qc + wc + np * 16 + brow_off, kb + bkb_off);
                uint32_t r0, r1, r2, r3;
                ldmx4(r0, r1, r2, r3, addr);
                b[np * 2][0] = r0; b[np * 2][1] = r1;
                b[np * 2 + 1][0] = r2; b[np * 2 + 1][1] = r3;
            }
            #pragma unroll
            for (int mt = 0; mt < 2; mt++)
                #pragma unroll
                for (int nt = 0; nt < 8; nt++)
                    mma16816(acc[mt][nt], a[mt][0], a[mt][1], a[mt][2], a[mt][3],
                             b[nt][0], b[nt][1]);
        }

        float qsum = 0.f;
        #pragma unroll
        for (int mt = 0; mt < 2; mt++) {
            int r0l = qr + wr + mt * 16 + lr;
            float sa0 = sq[r0l], sa1 = sq[r0l + 8];
            #pragma unroll
            for (int nt = 0; nt < 8; nt++) {
                int cl = qc + wc + nt * 8 + lc;
                float sb0 = sq[cl], sb1 = sq[cl + 1];
                float* c = acc[mt][nt];
                float d00 = sqrtf(fmaxf(sa0 + sb0 - 2.0f * c[0], 0.0f) + 1e-12f);
                float d01 = sqrtf(fmaxf(sa0 + sb1 - 2.0f * c[1], 0.0f) + 1e-12f);
                float d10 = sqrtf(fmaxf(sa1 + sb0 - 2.0f * c[2], 0.0f) + 1e-12f);
                float d11 = sqrtf(fmaxf(sa1 + sb1 - 2.0f * c[3], 0.0f) + 1e-12f);
                qsum += (d00 + d01) + (d10 + d11);
                __nv_bfloat162 p0 = __floats2bfloat162_rn(d00, d01);
                __nv_bfloat162 p1 = __floats2bfloat162_rn(d10, d11);
                *(uint32_t*)(Dslot + ((size_t)r0l << 8) + cl)       = *(uint32_t*)&p0;
                *(uint32_t*)(Dslot + ((size_t)(r0l + 8) << 8) + cl) = *(uint32_t*)&p1;
            }
        }
        tsum = fmaf(w, qsum, tsum);
    }

    #pragma unroll
    for (int off = 16; off > 0; off >>= 1)
        tsum += __shfl_down_sync(0xffffffffu, tsum, off);
    if (lane == 0) rsum[wid] = tsum;
    __syncthreads();
    if (tid == 0) {
        float tot = 0.f;
        #pragma unroll
        for (int w8 = 0; w8 < 8; w8++) tot += rsum[w8];
        g_sumD[s] = tot;
    }
}

// ---------------- hist inner: 12-bin ffma2 power-tree ----------------
struct HistCtx {
    unsigned long long sbin2, GA2, c16GA2, m2GA2, p8GA2, C2;
};
static __device__ __forceinline__ void hist_pair(const HistCtx& cx,
                                                 unsigned long long acc[NBINC],
                                                 float d0, float d1,
                                                 unsigned long long wv, bool weighted) {
    unsigned long long p = mul2(pk2(d0, d1), cx.sbin2);
    unsigned long long pg   = mul2(p, cx.GA2);
    unsigned long long arg0 = ffma2(pg, p, cx.c16GA2);     // GA p^2 - 16GA
    unsigned long long rarg = ffma2(p, cx.m2GA2, cx.p8GA2); // -2GA p + 8GA
    float a0l, a0h, rl, rh;
    up2(arg0, a0l, a0h); up2(rarg, rl, rh);
    unsigned long long t0 = pk2(ex2f(a0l), ex2f(a0h));
    unsigned long long rr = pk2(ex2f(rl), ex2f(rh));
    if (weighted) t0 = mul2(t0, wv);

    unsigned long long rr2 = mul2(rr, rr);
    unsigned long long rr4 = mul2(rr2, rr2);
    unsigned long long t1  = mul2(t0, rr);
    unsigned long long t2  = mul2(t0, rr2);
    unsigned long long t3  = mul2(t1, rr2);

    acc[0] = add2(acc[0], t0);
    acc[1] = add2(acc[1], t1);
    acc[2] = add2(acc[2], t2);
    acc[3] = add2(acc[3], t3);
    acc[4] = ffma2(t0, rr4, acc[4]);
    acc[5] = ffma2(t1, rr4, acc[5]);
    acc[6] = ffma2(t2, rr4, acc[6]);
    acc[7] = ffma2(t3, rr4, acc[7]);

    unsigned long long rr8 = mul2(rr4, rr4);
    unsigned long long t8  = mul2(t0, rr8);
    unsigned long long rC  = mul2(rr, cx.C2);
    unsigned long long rC2 = mul2(rC, rC);
    unsigned long long rC3 = mul2(rC2, rC);

    acc[8]  = add2(acc[8], t8);
    acc[9]  = ffma2(t8, rC,  acc[9]);
    acc[10] = ffma2(t8, rC2, acc[10]);
    acc[11] = ffma2(t8, rC3, acc[11]);
}

// ---------------- final reduction tail ----------------
static __device__ __forceinline__ void final_reduce(float* __restrict__ out, int t) {
    __shared__ float fred8[8];
    __shared__ float ftsave;
    int lane = t & 31, wrp = t >> 5;

    float v = 0.f;
    if (t < NG) {
        float h1[KBINS], h2[KBINS];
        float sA = 0.f, sB = 0.f;
        #pragma unroll
        for (int k = 0; k < KBINS; k++) {
            float dc = 256.0f * ex2f(GA * (float)(k * k));   // analytic diagonal
            float a = dc, b = dc;
            #pragma unroll
            for (int p = 0; p < 3; p++) {
                a += g_hpart[(t * 3 + p) * KBINS + k];
                b += g_hpart[((t + NG) * 3 + p) * KBINS + k];
            }
            h1[k] = a; h2[k] = b; sA += a; sB += b;
        }
        float iA = 1.f / (sA + 1e-8f), iB = 1.f / (sB + 1e-8f);
        float mm = 0.f;
        #pragma unroll
        for (int k = 0; k < KBINS; k++) {
            float d = h1[k] * iA - h2[k] * iB;
            mm += d * d;
        }
        v = mm * (1.0f / KBINS);
    }
    #pragma unroll
    for (int off = 16; off > 0; off >>= 1)
        v += __shfl_down_sync(0xffffffffu, v, off);
    if (lane == 0) fred8[wrp] = v;
    __syncthreads();
    if (t == 0) {
        float tot = 0.f;
        #pragma unroll
        for (int w8 = 0; w8 < 8; w8++) tot += fred8[w8];
        ftsave = tot;
    }
    __syncthreads();

    float r = g_rowloss[t];
    #pragma unroll
    for (int off = 16; off > 0; off >>= 1)
        r += __shfl_down_sync(0xffffffffu, r, off);
    __syncthreads();
    if (lane == 0) fred8[wrp] = r;
    __syncthreads();
    if (t == 0) {
        float tot = 0.f;
        #pragma unroll
        for (int w8 = 0; w8 < 8; w8++) tot += fred8[w8];
        float topo = ftsave * (1.0f / NG);
        float ntx  = tot * (1.0f / NSLOT);
        out[0] = LAMBDA * (topo + ntx);
    }
}

// ---------------- kernel 2: soft histogram (3 parts/slot) + ntxent(part0) + final ----------------
__global__ __launch_bounds__(256) void k_hist(float* __restrict__ out) {
    __shared__ int lastflag;
    __shared__ float4 zr4[32];
    __shared__ float sims[256];
    __shared__ float red8n[8];

    int bx = blockIdx.x;
    int s = bx / 3, part = bx - s * 3;
    int tid = threadIdx.x;
    int lane = tid & 31, wrp = tid >> 5;
    const uint4* Du4 = (const uint4*)(g_Dbf + ((size_t)s << 16));
    if (tid == 0) lastflag = 0;

    // ---- ntxent row s (part 0 blocks only) ----
    if (part == 0) {
        if (tid < 32) zr4[tid] = ((const float4*)(g_znR + (size_t)s * DF))[tid];
        __syncthreads();
        float acc = 0.f;
        #pragma unroll
        for (int k4 = 0; k4 < 32; k4++) {
            float4 b = g_znT4[k4 * NSLOT + tid];
            float4 a = zr4[k4];
            acc = fmaf(a.x, b.x, fmaf(a.y, b.y, fmaf(a.z, b.z, fmaf(a.w, b.w, acc))));
        }
        float sim = acc * INV_TEMP;
        if (tid == s) sim = -1e9f;
        sims[tid] = sim;

        float m = sim;
        #pragma unroll
        for (int off = 16; off > 0; off >>= 1)
            m = fmaxf(m, __shfl_xor_sync(0xffffffffu, m, off));
        if (lane == 0) red8n[wrp] = m;
        __syncthreads();
        float rmax = red8n[0];
        #pragma unroll
        for (int w8 = 1; w8 < 8; w8++) rmax = fmaxf(rmax, red8n[w8]);

        float e = __expf(sim - rmax);
        #pragma unroll
        for (int off = 16; off > 0; off >>= 1)
            e += __shfl_down_sync(0xffffffffu, e, off);
        __syncthreads();
        if (lane == 0) red8n[wrp] = e;
        __syncthreads();
        if (tid == 0) {
            float tot = 0.f;
            #pragma unroll
            for (int w8 = 0; w8 < 8; w8++) tot += red8n[w8];
            int label = (s < NG) ? s + NG : s - NG;
            g_rowloss[s] = rmax + logf(tot) - sims[label];
        }
    }

    // ---- histogram ----
    float mean = g_sumD[s] * (1.0f / 65536.0f);
    float sbin = 5.0f / (mean + 1e-8f);

    HistCtx cx;
    cx.sbin2  = pk2(sbin, sbin);
    cx.GA2    = pk2(GA, GA);
    cx.c16GA2 = pk2(-16.0f * GA, -16.0f * GA);
    cx.m2GA2  = pk2(-2.0f * GA, -2.0f * GA);
    cx.p8GA2  = pk2(8.0f * GA, 8.0f * GA);
    float Cs = ex2f(16.0f * GA);
    cx.C2 = pk2(Cs, Cs);

    unsigned long long acc[NBINC];
    #pragma unroll
    for (int k = 0; k < NBINC; k++) acc[k] = 0ULL;

    if (part == 0) {
        // cross quadrant rows 0..127, cols 128..255 (uniform weight; MLP=2)
        #pragma unroll 1
        for (int it = 0; it < 8; it += 2) {
            int i0 = it * 256 + tid;
            int i1 = i0 + 256;
            uint4 va = Du4[((i0 >> 4) << 5) + (i0 & 15) + 16];
            uint4 vb = Du4[((i1 >> 4) << 5) + (i1 & 15) + 16];
            uint32_t pwa[4] = {va.x, va.y, va.z, va.w};
            uint32_t pwb[4] = {vb.x, vb.y, vb.z, vb.w};
            #pragma unroll
            for (int e = 0; e < 4; e++) {
                float2 f = __bfloat1622float2(*(__nv_bfloat162*)&pwa[e]);
                hist_pair(cx, acc, f.x, f.y, 0ULL, false);
            }
            #pragma unroll
            for (int e = 0; e < 4; e++) {
                float2 f = __bfloat1622float2(*(__nv_bfloat162*)&pwb[e]);
                hist_pair(cx, acc, f.x, f.y, 0ULL, false);
            }
        }
    } else {
        // strict-upper triangle of diag quadrant (part 1 -> quad 0, part 2 -> quad 1)
        int quad = part - 1;
        int rowoff = quad << 7;
        int ucol = quad << 4;

        // (a) diagonal u4 blocks, per-element weight 1/0 (only place with predication)
        if (tid < 128) {
            int row = tid;
            int c4 = row >> 3;
            uint4 v = Du4[((rowoff + row) << 5) + ucol + c4];
            uint32_t pw[4] = {v.x, v.y, v.z, v.w};
            #pragma unroll
            for (int e = 0; e < 4; e++) {
                int j = (c4 << 3) + e * 2;
                float2 f = __bfloat1622float2(*(__nv_bfloat162*)&pw[e]);
                float wlo = (j     > row) ? 1.0f : 0.0f;
                float whi = (j + 1 > row) ? 1.0f : 0.0f;
                hist_pair(cx, acc, f.x, f.y, pk2(wlo, whi), true);
            }
        }

        // (b) strictly-above blocks: uniform weight, no predication
        int h = tid & 63;
        int par4 = tid >> 6;          // 0..3
        #pragma unroll 1
        for (int half = 0; half < 2; half++) {
            int row = half ? (127 - h) : h;
            int cmin = row >> 3;      // skip c4 <= cmin (diag handled above)
            #pragma unroll 1
            for (int c4 = par4; c4 < 16; c4 += 4) {
                if (c4 <= cmin) continue;
                uint4 v = Du4[((rowoff + row) << 5) + ucol + c4];
                uint32_t pw[4] = {v.x, v.y, v.z, v.w};
                #pragma unroll
                for (int e = 0; e < 4; e++) {
                    float2 f = __bfloat1622float2(*(__nv_bfloat162*)&pw[e]);
                    hist_pair(cx, acc, f.x, f.y, 0ULL, false);
                }
            }
        }
    }

    __shared__ float hsm[8][NBINC];
    #pragma unroll
    for (int k = 0; k < NBINC; k++) {
        int ctr = (k < 8) ? 4 : 12;
        float sc = ex2f(GA * (float)((k - ctr) * (k - ctr)));
        float lo, hi;
        up2(acc[k], lo, hi);
        float v = (lo + hi) * sc;
        #pragma unroll
        for (int off = 16; off > 0; off >>= 1)
            v += __shfl_down_sync(0xffffffffu, v, off);
        if ((tid & 31) == 0) hsm[tid >> 5][k] = v;
    }
    __syncthreads();
    if (tid < KBINS) {
        float t = 0.f;
        if (tid < NBINC) {
            #pragma unroll
            for (int w8 = 0; w8 < 8; w8++) t += hsm[w8][tid];
            t *= 2.0f;                 // all parts carry weight 2 (cross / upper-triangle)
        }
        g_hpart[(s * 3 + part) * KBINS + tid] = t;
    }
    if (tid == 0) {
        __threadfence();
        int old = atomicAdd(&g_ticket, 1);
        if (old == 3 * NSLOT - 1) lastflag = 1;
    }
    __syncthreads();
    if (!lastflag) return;

    final_reduce(out, tid);
}

// ---------------- launcher ----------------
extern "C" void kernel_launch(void* const* d_in, const int* in_sizes, int n_in,
                              void* d_out, int out_size) {
    const float* H1 = (const float*)d_in[0];
    const float* H2 = (const float*)d_in[2];
    const float* z1 = (const float*)d_in[4];
    const float* z2 = (const float*)d_in[5];
    float* out = (float*)d_out;

    cudaFuncSetAttribute(k_gemm, cudaFuncAttributeMaxDynamicSharedMemorySize, 65536);

    k_gemm<<<NSLOT, 256, 65536>>>(H1, H2, z1, z2);
    k_hist<<<NSLOT * 3, 256>>>(out);
}